// round 6
// baseline (speedup 1.0000x reference)
#include <cuda_runtime.h>
#include <cuda_fp16.h>
#include <cstdint>
#include <cstddef>

#define HD   128
#define NMAX 100000
#define GMAX 1024
#define ELLW 64

// ---------------- scratch (device globals; no allocation allowed) ----------
__device__ __align__(256) float  g_buf0[NMAX * HD];     // h f32 (last layer)
__device__ __align__(256) __half g_msg[NMAX * HD];      // m' = fp16( (h@W) * dinv[row] )
__device__ __align__(256) __half g_h[NMAX * HD];        // h fp16 (GEMM A input)
__device__ __align__(256) __half g_whi[4 * HD * HD];    // W^T fp16 hi ([N,K] row-major)
__device__ __align__(256) __half g_wlo[4 * HD * HD];    // W^T fp16 lo
__device__ __align__(256) int   g_ell[NMAX * ELLW];
__device__ __align__(256) int   g_cnt[NMAX];
__device__ __align__(256) float g_dinv[NMAX];
__device__ __align__(256) float g_pooled[GMAX * HD];
__device__ __align__(256) float g_counts[GMAX];

// ---------------- helpers ----------------------------------------------------
__device__ __forceinline__ uint32_t smem_u32(const void* p) {
    uint32_t a;
    asm("{ .reg .u64 t; cvta.to.shared.u64 t, %1; cvt.u32.u64 %0, t; }" : "=r"(a) : "l"(p));
    return a;
}

__device__ __forceinline__ void ldm4(uint32_t* r, uint32_t addr) {
    asm volatile("ldmatrix.sync.aligned.m8n8.x4.shared.b16 {%0,%1,%2,%3}, [%4];"
                 : "=r"(r[0]), "=r"(r[1]), "=r"(r[2]), "=r"(r[3]) : "r"(addr));
}

__device__ __forceinline__ void mma_f16(float* c, const uint32_t* a,
                                        uint32_t b0, uint32_t b1) {
    asm volatile(
        "mma.sync.aligned.m16n8k16.row.col.f32.f16.f16.f32 "
        "{%0,%1,%2,%3}, {%4,%5,%6,%7}, {%8,%9}, {%0,%1,%2,%3};"
        : "+f"(c[0]), "+f"(c[1]), "+f"(c[2]), "+f"(c[3])
        : "r"(a[0]), "r"(a[1]), "r"(a[2]), "r"(a[3]), "r"(b0), "r"(b1));
}

// SMEM plan: padded rows, stride 136 fp16 = 272 bytes (conflict-free ldmatrix)
#define ROWB 272
#define SA    0
#define SW_HI (SA + 64 * ROWB)
#define SW_LO (SW_HI + 128 * ROWB)
#define S_TOT (SW_LO + 128 * ROWB)

// ---------------- HMMA GEMM: M[r,:] = fp16( (A[r,:] @ W) * dinv[r] ) --------
// A fp16 [n,128]; W^T fp16 hi/lo [128,128] ([N,K] row-major).
// block tile: 64m x 128n, 8 warps = 4 m-strips x 2 n-halves, full K=128.
__global__ __launch_bounds__(256, 2) void gemm_hmma(
    const __half* __restrict__ A,
    const __half* __restrict__ Whi, const __half* __restrict__ Wlo,
    const float* __restrict__ dinv, __half* __restrict__ M, int n)
{
    extern __shared__ char smem[];
    const uint32_t sb = smem_u32(smem);
    const int tid = threadIdx.x;
    const int row0 = blockIdx.x * 64;

    // ---- load tiles ----
    const uint4 z4 = make_uint4(0, 0, 0, 0);
#pragma unroll
    for (int i = 0; i < 4; i++) {                    // A: 64 rows x 16 uint4
        int idx = tid + i * 256;
        int r = idx >> 4, c = idx & 15;
        int gr = row0 + r;
        uint4 v = z4;
        if (gr < n) v = *(const uint4*)(A + (size_t)gr * HD + c * 8);
        *(uint4*)(smem + SA + r * ROWB + c * 16) = v;
    }
#pragma unroll
    for (int i = 0; i < 8; i++) {                    // W hi+lo: 128 rows x 16 uint4 each
        int idx = tid + i * 256;
        int r = idx >> 4, c = idx & 15;
        *(uint4*)(smem + SW_HI + r * ROWB + c * 16) =
            *(const uint4*)(Whi + (size_t)r * HD + c * 8);
        *(uint4*)(smem + SW_LO + r * ROWB + c * 16) =
            *(const uint4*)(Wlo + (size_t)r * HD + c * 8);
    }
    __syncthreads();

    // ---- compute ----
    const int wid = tid >> 5, lane = tid & 31;
    const int mstrip = wid & 3;
    const int nhalf  = wid >> 2;
    const int lrow = lane & 15, lcol = lane >> 4;

    float acc[8][4];
#pragma unroll
    for (int p = 0; p < 8; p++)
#pragma unroll
        for (int j = 0; j < 4; j++) acc[p][j] = 0.0f;

    const uint32_t a0   = sb + SA    + (mstrip * 16 + lrow) * ROWB + lcol * 16;
    const uint32_t w_hi0 = sb + SW_HI + (nhalf * 64 + lrow) * ROWB + lcol * 16;
    const uint32_t w_lo0 = sb + SW_LO + (nhalf * 64 + lrow) * ROWB + lcol * 16;

#pragma unroll
    for (int ks = 0; ks < 8; ks++) {
        uint32_t a[4];
        ldm4(a, a0 + ks * 32);
#pragma unroll
        for (int p = 0; p < 4; p++) {
            uint32_t wh[4], wl[4];
            ldm4(wh, w_hi0 + p * (16 * ROWB) + ks * 32);
            mma_f16(acc[2 * p],     a, wh[0], wh[2]);
            mma_f16(acc[2 * p + 1], a, wh[1], wh[3]);
            ldm4(wl, w_lo0 + p * (16 * ROWB) + ks * 32);
            mma_f16(acc[2 * p],     a, wl[0], wl[2]);
            mma_f16(acc[2 * p + 1], a, wl[1], wl[3]);
        }
    }

    // ---- epilogue: scale by dinv[row], store fp16 ----
    const int rbase = row0 + mstrip * 16 + (lane >> 2);
    const int qc = (lane & 3) * 2;
#pragma unroll
    for (int rr = 0; rr < 2; rr++) {
        int row = rbase + rr * 8;
        if (row < n) {
            float w = dinv[row];
            __half* dst = M + (size_t)row * HD + nhalf * 64 + qc;
#pragma unroll
            for (int p = 0; p < 8; p++) {
                __half2 v = __floats2half2_rn(acc[p][rr * 2] * w, acc[p][rr * 2 + 1] * w);
                *(__half2*)(dst + p * 8) = v;
            }
        }
    }
}

// ---------------- graph build ------------------------------------------------
__global__ void zero_cnt(int* __restrict__ cnt, int n) {
    int i = blockIdx.x * blockDim.x + threadIdx.x;
    if (i < n) cnt[i] = 0;
}

__global__ void fill_ell(const int* __restrict__ src, const int* __restrict__ dst,
                         int* __restrict__ cnt, int* __restrict__ ell, int E)
{
    int e = blockIdx.x * blockDim.x + threadIdx.x;
    if (e >= E) return;
    int d = dst[e];
    int pos = atomicAdd(&cnt[d], 1);
    if (pos < ELLW) ell[(size_t)d * ELLW + pos] = src[e];
}

__global__ void make_dinv(const int* __restrict__ cnt, float* __restrict__ dinv, int n) {
    int i = blockIdx.x * blockDim.x + threadIdx.x;
    if (i < n) dinv[i] = rsqrtf((float)cnt[i] + 1.0f);
}

// ---------------- weight split + transpose (all 4 layers, one launch) -------
__global__ void wsplit4(const float* __restrict__ W0, const float* __restrict__ W1,
                        const float* __restrict__ W2, const float* __restrict__ W3,
                        __half* __restrict__ Bhi, __half* __restrict__ Blo)
{
    int idx = blockIdx.x * blockDim.x + threadIdx.x;
    if (idx >= 4 * HD * HD) return;
    int l = idx >> 14;
    int r = idx & (HD * HD - 1);
    const float* W = (l == 0) ? W0 : (l == 1) ? W1 : (l == 2) ? W2 : W3;
    int nn = r >> 7, kk = r & 127;
    float v = W[kk * HD + nn];
    __half hi = __float2half_rn(v);
    __half lo = __float2half_rn(v - __half2float(hi));
    Bhi[idx] = hi;
    Blo[idx] = lo;
}

// ---------------- input convert: x -> fp16 ------------------------------------
__global__ void xtof16(const float* __restrict__ x, __half* __restrict__ h, int total) {
    int i = blockIdx.x * blockDim.x + threadIdx.x;
    if (i >= total) return;
    h[i] = __float2half_rn(x[i]);
}

// ---------------- fused gather + selfloop + bias + relu ----------------------
// one warp per dst node, fp16 messages: lane covers 4 channels (8 bytes)
__global__ __launch_bounds__(256) void gather_nodes(
    const __half* __restrict__ m, const int* __restrict__ ell,
    const int* __restrict__ cnt, const float* __restrict__ dinv,
    const float* __restrict__ bias,
    __half* __restrict__ out_h, float* __restrict__ out_f32, int mode, int n)
{
    int d = blockIdx.x * (blockDim.x >> 5) + (threadIdx.x >> 5);
    if (d >= n) return;
    const int lane = threadIdx.x & 31;
    const int c4 = lane << 2;

    // self term
    uint2 sraw = *(const uint2*)(m + (size_t)d * HD + c4);
    float2 s0 = __half22float2(*(const __half2*)&sraw.x);
    float2 s1 = __half22float2(*(const __half2*)&sraw.y);
    float a0 = s0.x, a1 = s0.y, a2 = s1.x, a3 = s1.y;

    const int deg = cnt[d];
    const int* row = ell + (size_t)d * ELLW;

    for (int base = 0; base < deg; base += 32) {
        int idx = (base + lane < deg) ? __ldg(row + base + lane) : 0;
        int lim = min(32, deg - base);
#pragma unroll 8
        for (int j = 0; j < lim; j++) {
            int s = __shfl_sync(0xffffffffu, idx, j);
            uint2 raw = *(const uint2*)(m + (size_t)s * HD + c4);
            float2 v0 = __half22float2(*(const __half2*)&raw.x);
            float2 v1 = __half22float2(*(const __half2*)&raw.y);
            a0 += v0.x; a1 += v0.y; a2 += v1.x; a3 += v1.y;
        }
    }

    float w = dinv[d];
    float4 bb = *(const float4*)(bias + c4);
    float o0 = fmaxf(fmaf(a0, w, bb.x), 0.f);
    float o1 = fmaxf(fmaf(a1, w, bb.y), 0.f);
    float o2 = fmaxf(fmaf(a2, w, bb.z), 0.f);
    float o3 = fmaxf(fmaf(a3, w, bb.w), 0.f);

    if (mode == 0) {
        __half2 h0 = __floats2half2_rn(o0, o1);
        __half2 h1 = __floats2half2_rn(o2, o3);
        *(__half2*)(out_h + (size_t)d * HD + c4)     = h0;
        *(__half2*)(out_h + (size_t)d * HD + c4 + 2) = h1;
    } else {
        *(float4*)(out_f32 + (size_t)d * HD + c4) = make_float4(o0, o1, o2, o3);
    }
}

// ---------------- pooling ------------------------------------------------------
__global__ void zero_pool(float* __restrict__ pooled, float* __restrict__ counts, int G) {
    int i = blockIdx.x * blockDim.x + threadIdx.x;
    if (i < G * HD) pooled[i] = 0.0f;
    if (i < G) counts[i] = 0.0f;
}

__global__ void pool_nodes(const float* __restrict__ h, const int* __restrict__ batch,
                           float* __restrict__ pooled, float* __restrict__ counts, int n)
{
    int i = blockIdx.x * (blockDim.x >> 5) + (threadIdx.x >> 5);
    if (i >= n) return;
    int lane = threadIdx.x & 31;
    int g = batch[i];
    float4 v = *(const float4*)(h + (size_t)i * HD + (lane << 2));
    float* p = pooled + (size_t)g * HD + (lane << 2);
    asm volatile("red.global.add.v4.f32 [%0], {%1, %2, %3, %4};"
                 :: "l"(p), "f"(v.x), "f"(v.y), "f"(v.z), "f"(v.w) : "memory");
    if (lane == 0) atomicAdd(&counts[g], 1.0f);
}

// ---------------- final linear head --------------------------------------------
__global__ void final_linear(const float* __restrict__ pooled, const float* __restrict__ counts,
                             const float* __restrict__ linW, const float* __restrict__ linb,
                             float* __restrict__ out)
{
    int g = blockIdx.x;
    int c = threadIdx.x;
    float cntv = fmaxf(counts[g], 1.0f);
    float p = pooled[g * HD + c] / cntv;
    float v0 = p * linW[c * 2 + 0];
    float v1 = p * linW[c * 2 + 1];
#pragma unroll
    for (int o = 16; o > 0; o >>= 1) {
        v0 += __shfl_xor_sync(0xffffffffu, v0, o);
        v1 += __shfl_xor_sync(0xffffffffu, v1, o);
    }
    __shared__ float s0[4], s1[4];
    int w = threadIdx.x >> 5;
    if ((threadIdx.x & 31) == 0) { s0[w] = v0; s1[w] = v1; }
    __syncthreads();
    if (threadIdx.x == 0) {
        out[g * 2 + 0] = s0[0] + s0[1] + s0[2] + s0[3] + linb[0];
        out[g * 2 + 1] = s1[0] + s1[1] + s1[2] + s1[3] + linb[1];
    }
}

// ---------------- launch ---------------------------------------------------------
extern "C" void kernel_launch(void* const* d_in, const int* in_sizes, int n_in,
                              void* d_out, int out_size)
{
    const float* x     = (const float*)d_in[0];
    const int*   ei    = (const int*)d_in[1];
    const int*   batch = (const int*)d_in[2];
    const float* W[4]  = {(const float*)d_in[3], (const float*)d_in[5],
                          (const float*)d_in[7], (const float*)d_in[9]};
    const float* bv[4] = {(const float*)d_in[4], (const float*)d_in[6],
                          (const float*)d_in[8], (const float*)d_in[10]};
    const float* linW  = (const float*)d_in[11];
    const float* linb  = (const float*)d_in[12];
    float* out = (float*)d_out;

    const int n = in_sizes[0] / HD;
    const int E = in_sizes[1] / 2;
    const int G = out_size / 2;
    const int* src = ei;
    const int* dst = ei + E;

    float *buf0, *dinv, *pooled, *counts;
    __half *msg, *hbuf, *whi, *wlo;
    int *ell, *cnt;
    cudaGetSymbolAddress((void**)&buf0,   g_buf0);
    cudaGetSymbolAddress((void**)&msg,    g_msg);
    cudaGetSymbolAddress((void**)&hbuf,   g_h);
    cudaGetSymbolAddress((void**)&whi,    g_whi);
    cudaGetSymbolAddress((void**)&wlo,    g_wlo);
    cudaGetSymbolAddress((void**)&ell,    g_ell);
    cudaGetSymbolAddress((void**)&cnt,    g_cnt);
    cudaGetSymbolAddress((void**)&dinv,   g_dinv);
    cudaGetSymbolAddress((void**)&pooled, g_pooled);
    cudaGetSymbolAddress((void**)&counts, g_counts);

    cudaFuncSetAttribute(gemm_hmma, cudaFuncAttributeMaxDynamicSharedMemorySize, S_TOT);

    // graph build + weight split + input convert
    zero_cnt<<<(n + 255) / 256, 256>>>(cnt, n);
    fill_ell<<<(E + 255) / 256, 256>>>(src, dst, cnt, ell, E);
    make_dinv<<<(n + 255) / 256, 256>>>(cnt, dinv, n);
    wsplit4<<<(4 * HD * HD + 255) / 256, 256>>>(W[0], W[1], W[2], W[3], whi, wlo);
    xtof16<<<(n * HD + 255) / 256, 256>>>(x, hbuf, n * HD);

    const int tiles = (n + 63) / 64;
    for (int l = 0; l < 4; l++) {
        gemm_hmma<<<tiles, 256, S_TOT>>>(hbuf, whi + l * HD * HD, wlo + l * HD * HD,
                                         dinv, msg, n);
        gather_nodes<<<(n + 7) / 8, 256>>>(msg, ell, cnt, dinv, bv[l],
                                           hbuf, buf0, (l == 3) ? 1 : 0, n);
    }

    zero_pool<<<(G * HD + 255) / 256, 256>>>(pooled, counts, G);
    pool_nodes<<<(n + 7) / 8, 256>>>(buf0, batch, pooled, counts, n);
    final_linear<<<G, 128>>>(pooled, counts, linW, linb, out);
}

// round 7
// speedup vs baseline: 1.2077x; 1.2077x over previous
#include <cuda_runtime.h>
#include <cuda_bf16.h>
#include <cuda_fp16.h>
#include <cstdint>
#include <cstddef>

#define HD   128
#define NMAX 100000
#define GMAX 1024
#define ELLW 64

// ---------------- scratch (device globals; no allocation allowed) ----------
__device__ __align__(256) float  g_buf0[NMAX * HD];           // h f32 (last layer)
__device__ __align__(256) __half g_msg[NMAX * HD];            // m' fp16 = (h @ W) * dinv[row]
__device__ __align__(256) __nv_bfloat16 g_hi[NMAX * HD];      // h split hi
__device__ __align__(256) __nv_bfloat16 g_lo[NMAX * HD];      // h split lo
__device__ __align__(256) __nv_bfloat16 g_whi[4 * HD * HD];   // W^T split hi ([N,K] row-major)
__device__ __align__(256) __nv_bfloat16 g_wlo[4 * HD * HD];   // W^T split lo
__device__ __align__(256) int   g_ell[NMAX * ELLW];
__device__ __align__(256) int   g_cnt[NMAX];
__device__ __align__(256) float g_dinv[NMAX];
__device__ __align__(256) float g_pooled[GMAX * HD];
__device__ __align__(256) float g_counts[GMAX];

// ---------------- helpers ----------------------------------------------------
__device__ __forceinline__ uint32_t smem_u32(const void* p) {
    uint32_t a;
    asm("{ .reg .u64 t; cvta.to.shared.u64 t, %1; cvt.u32.u64 %0, t; }" : "=r"(a) : "l"(p));
    return a;
}

__device__ __forceinline__ void ldm4(uint32_t* r, uint32_t addr) {
    asm volatile("ldmatrix.sync.aligned.m8n8.x4.shared.b16 {%0,%1,%2,%3}, [%4];"
                 : "=r"(r[0]), "=r"(r[1]), "=r"(r[2]), "=r"(r[3]) : "r"(addr));
}

__device__ __forceinline__ void mma_bf16(float* c, const uint32_t* a,
                                         uint32_t b0, uint32_t b1) {
    asm volatile(
        "mma.sync.aligned.m16n8k16.row.col.f32.bf16.bf16.f32 "
        "{%0,%1,%2,%3}, {%4,%5,%6,%7}, {%8,%9}, {%0,%1,%2,%3};"
        : "+f"(c[0]), "+f"(c[1]), "+f"(c[2]), "+f"(c[3])
        : "r"(a[0]), "r"(a[1]), "r"(a[2]), "r"(a[3]), "r"(b0), "r"(b1));
}

// SMEM plan: padded rows, stride 136 bf16 = 272 bytes (conflict-free ldmatrix)
#define ROWB 272
#define SA_HI 0
#define SA_LO (SA_HI + 64 * ROWB)
#define SW_HI (SA_LO + 64 * ROWB)
#define SW_LO (SW_HI + 128 * ROWB)
#define S_TOT (SW_LO + 128 * ROWB)

// ---------------- HMMA GEMM: M[r,:] = fp16( (A[r,:] @ W) * dinv[r] ) --------
// (identical to the proven R5 kernel: 3-pass bf16 split)
__global__ __launch_bounds__(256, 2) void gemm_hmma(
    const __nv_bfloat16* __restrict__ Ahi, const __nv_bfloat16* __restrict__ Alo,
    const __nv_bfloat16* __restrict__ Whi, const __nv_bfloat16* __restrict__ Wlo,
    const float* __restrict__ dinv, __half* __restrict__ M, int n)
{
    extern __shared__ char smem[];
    const uint32_t sb = smem_u32(smem);
    const int tid = threadIdx.x;
    const int row0 = blockIdx.x * 64;

    const uint4 z4 = make_uint4(0, 0, 0, 0);
#pragma unroll
    for (int i = 0; i < 4; i++) {                    // A: 64 rows x 16 uint4
        int idx = tid + i * 256;
        int r = idx >> 4, c = idx & 15;
        int gr = row0 + r;
        uint4 vh = z4, vl = z4;
        if (gr < n) {
            vh = *(const uint4*)(Ahi + (size_t)gr * HD + c * 8);
            vl = *(const uint4*)(Alo + (size_t)gr * HD + c * 8);
        }
        *(uint4*)(smem + SA_HI + r * ROWB + c * 16) = vh;
        *(uint4*)(smem + SA_LO + r * ROWB + c * 16) = vl;
    }
#pragma unroll
    for (int i = 0; i < 8; i++) {                    // W: 128 rows x 16 uint4
        int idx = tid + i * 256;
        int r = idx >> 4, c = idx & 15;
        *(uint4*)(smem + SW_HI + r * ROWB + c * 16) =
            *(const uint4*)(Whi + (size_t)r * HD + c * 8);
        *(uint4*)(smem + SW_LO + r * ROWB + c * 16) =
            *(const uint4*)(Wlo + (size_t)r * HD + c * 8);
    }
    __syncthreads();

    const int wid = tid >> 5, lane = tid & 31;
    const int mstrip = wid & 3;
    const int nhalf  = wid >> 2;
    const int lrow = lane & 15, lcol = lane >> 4;

    float acc[8][4];
#pragma unroll
    for (int p = 0; p < 8; p++)
#pragma unroll
        for (int j = 0; j < 4; j++) acc[p][j] = 0.0f;

    const uint32_t a_hi0 = sb + SA_HI + (mstrip * 16 + lrow) * ROWB + lcol * 16;
    const uint32_t a_lo0 = sb + SA_LO + (mstrip * 16 + lrow) * ROWB + lcol * 16;
    const uint32_t w_hi0 = sb + SW_HI + (nhalf * 64 + lrow) * ROWB + lcol * 16;
    const uint32_t w_lo0 = sb + SW_LO + (nhalf * 64 + lrow) * ROWB + lcol * 16;

#pragma unroll
    for (int ks = 0; ks < 8; ks++) {
        uint32_t ah[4], al[4];
        ldm4(ah, a_hi0 + ks * 32);
        ldm4(al, a_lo0 + ks * 32);
#pragma unroll
        for (int p = 0; p < 4; p++) {
            uint32_t wh[4], wl[4];
            ldm4(wh, w_hi0 + p * (16 * ROWB) + ks * 32);
            mma_bf16(acc[2 * p],     ah, wh[0], wh[2]);
            mma_bf16(acc[2 * p + 1], ah, wh[1], wh[3]);
            mma_bf16(acc[2 * p],     al, wh[0], wh[2]);
            mma_bf16(acc[2 * p + 1], al, wh[1], wh[3]);
            ldm4(wl, w_lo0 + p * (16 * ROWB) + ks * 32);
            mma_bf16(acc[2 * p],     ah, wl[0], wl[2]);
            mma_bf16(acc[2 * p + 1], ah, wl[1], wl[3]);
        }
    }

    const int rbase = row0 + mstrip * 16 + (lane >> 2);
    const int qc = (lane & 3) * 2;
#pragma unroll
    for (int rr = 0; rr < 2; rr++) {
        int row = rbase + rr * 8;
        if (row < n) {
            float w = dinv[row];
            __half* dst = M + (size_t)row * HD + nhalf * 64 + qc;
#pragma unroll
            for (int p = 0; p < 8; p++) {
                __half2 v = __floats2half2_rn(acc[p][rr * 2] * w, acc[p][rr * 2 + 1] * w);
                *(__half2*)(dst + p * 8) = v;
            }
        }
    }
}

// ---------------- graph build ------------------------------------------------
__global__ void zero_cnt(int* __restrict__ cnt, int n) {
    int i = blockIdx.x * blockDim.x + threadIdx.x;
    if (i < n) cnt[i] = 0;
}

__global__ void fill_ell(const int* __restrict__ src, const int* __restrict__ dst,
                         int* __restrict__ cnt, int* __restrict__ ell, int E)
{
    int e = blockIdx.x * blockDim.x + threadIdx.x;
    if (e >= E) return;
    int d = dst[e];
    int pos = atomicAdd(&cnt[d], 1);
    if (pos < ELLW) ell[(size_t)d * ELLW + pos] = src[e];
}

__global__ void make_dinv(const int* __restrict__ cnt, float* __restrict__ dinv, int n) {
    int i = blockIdx.x * blockDim.x + threadIdx.x;
    if (i < n) dinv[i] = rsqrtf((float)cnt[i] + 1.0f);
}

// ---------------- weight split + transpose (all 4 layers in one launch) -----
__global__ void wsplit4(const float* __restrict__ W0, const float* __restrict__ W1,
                        const float* __restrict__ W2, const float* __restrict__ W3,
                        __nv_bfloat16* __restrict__ Bhi, __nv_bfloat16* __restrict__ Blo)
{
    int idx = blockIdx.x * blockDim.x + threadIdx.x;
    if (idx >= 4 * HD * HD) return;
    int l = idx >> 14;
    int r = idx & (HD * HD - 1);
    const float* W = (l == 0) ? W0 : (l == 1) ? W1 : (l == 2) ? W2 : W3;
    int nn = r >> 7, kk = r & 127;
    float v = W[kk * HD + nn];
    __nv_bfloat16 hi = __float2bfloat16(v);
    __nv_bfloat16 lo = __float2bfloat16(v - __bfloat162float(hi));
    Bhi[idx] = hi;
    Blo[idx] = lo;
}

// ---------------- input split ------------------------------------------------
__global__ void xsplit(const float* __restrict__ x, __nv_bfloat16* __restrict__ hi,
                       __nv_bfloat16* __restrict__ lo, int total)
{
    int i = blockIdx.x * blockDim.x + threadIdx.x;
    if (i >= total) return;
    float v = x[i];
    __nv_bfloat16 h = __float2bfloat16(v);
    hi[i] = h;
    lo[i] = __float2bfloat16(v - __bfloat162float(h));
}

// ---------------- fused gather + selfloop + bias + relu (+ hi/lo split) -----
// HALF-WARP per dst node: 16 lanes x 16B (uint4 = 8 fp16 channels) per row.
// Two independent nodes per warp -> 2x MLP and half the broadcast serialization.
__global__ __launch_bounds__(256) void gather_nodes(
    const __half* __restrict__ m, const int* __restrict__ ell,
    const int* __restrict__ cnt, const float* __restrict__ dinv,
    const float* __restrict__ bias,
    __nv_bfloat16* __restrict__ out_hi, __nv_bfloat16* __restrict__ out_lo,
    float* __restrict__ out_f32, int mode, int n)
{
    const int hw   = threadIdx.x >> 4;               // half-warp id in block (0..15)
    const int d    = blockIdx.x * 16 + hw;
    if (d >= n) return;
    const int l16  = threadIdx.x & 15;               // lane in half-warp
    const int half = (threadIdx.x >> 4) & 1;         // which half of the warp
    const unsigned mask = 0xFFFFu << (half * 16);
    const int c8 = l16 << 3;                         // 8 fp16 channels per lane

    // self term
    uint4 sraw = *(const uint4*)(m + (size_t)d * HD + c8);
    float2 f0 = __half22float2(*(const __half2*)&sraw.x);
    float2 f1 = __half22float2(*(const __half2*)&sraw.y);
    float2 f2 = __half22float2(*(const __half2*)&sraw.z);
    float2 f3 = __half22float2(*(const __half2*)&sraw.w);
    float a0 = f0.x, a1 = f0.y, a2 = f1.x, a3 = f1.y;
    float a4 = f2.x, a5 = f2.y, a6 = f3.x, a7 = f3.y;

    const int deg = cnt[d];
    const int* row = ell + (size_t)d * ELLW;
    const int srcbase = half * 16;                   // absolute lane of group's lane 0

    for (int base = 0; base < deg; base += 16) {
        int idx = (base + l16 < deg) ? __ldg(row + base + l16) : 0;
        int lim = min(16, deg - base);
#pragma unroll 8
        for (int j = 0; j < lim; j++) {
            int s = __shfl_sync(mask, idx, srcbase + j);
            uint4 raw = *(const uint4*)(m + (size_t)s * HD + c8);
            float2 v0 = __half22float2(*(const __half2*)&raw.x);
            float2 v1 = __half22float2(*(const __half2*)&raw.y);
            float2 v2 = __half22float2(*(const __half2*)&raw.z);
            float2 v3 = __half22float2(*(const __half2*)&raw.w);
            a0 += v0.x; a1 += v0.y; a2 += v1.x; a3 += v1.y;
            a4 += v2.x; a5 += v2.y; a6 += v3.x; a7 += v3.y;
        }
    }

    float w = dinv[d];
    float4 b0 = *(const float4*)(bias + c8);
    float4 b1 = *(const float4*)(bias + c8 + 4);
    float o0 = fmaxf(fmaf(a0, w, b0.x), 0.f);
    float o1 = fmaxf(fmaf(a1, w, b0.y), 0.f);
    float o2 = fmaxf(fmaf(a2, w, b0.z), 0.f);
    float o3 = fmaxf(fmaf(a3, w, b0.w), 0.f);
    float o4 = fmaxf(fmaf(a4, w, b1.x), 0.f);
    float o5 = fmaxf(fmaf(a5, w, b1.y), 0.f);
    float o6 = fmaxf(fmaf(a6, w, b1.z), 0.f);
    float o7 = fmaxf(fmaf(a7, w, b1.w), 0.f);

    if (mode == 0) {
        __nv_bfloat16 h0 = __float2bfloat16(o0), h1 = __float2bfloat16(o1);
        __nv_bfloat16 h2 = __float2bfloat16(o2), h3 = __float2bfloat16(o3);
        __nv_bfloat16 h4 = __float2bfloat16(o4), h5 = __float2bfloat16(o5);
        __nv_bfloat16 h6 = __float2bfloat16(o6), h7 = __float2bfloat16(o7);
        __nv_bfloat162 hv[4] = {{h0, h1}, {h2, h3}, {h4, h5}, {h6, h7}};
        __nv_bfloat162 lv[4] = {
            {__float2bfloat16(o0 - __bfloat162float(h0)), __float2bfloat16(o1 - __bfloat162float(h1))},
            {__float2bfloat16(o2 - __bfloat162float(h2)), __float2bfloat16(o3 - __bfloat162float(h3))},
            {__float2bfloat16(o4 - __bfloat162float(h4)), __float2bfloat16(o5 - __bfloat162float(h5))},
            {__float2bfloat16(o6 - __bfloat162float(h6)), __float2bfloat16(o7 - __bfloat162float(h7))}};
        *(uint4*)(out_hi + (size_t)d * HD + c8) = *(const uint4*)hv;
        *(uint4*)(out_lo + (size_t)d * HD + c8) = *(const uint4*)lv;
    } else {
        *(float4*)(out_f32 + (size_t)d * HD + c8)     = make_float4(o0, o1, o2, o3);
        *(float4*)(out_f32 + (size_t)d * HD + c8 + 4) = make_float4(o4, o5, o6, o7);
    }
}

// ---------------- pooling ------------------------------------------------------
__global__ void zero_pool(float* __restrict__ pooled, float* __restrict__ counts, int G) {
    int i = blockIdx.x * blockDim.x + threadIdx.x;
    if (i < G * HD) pooled[i] = 0.0f;
    if (i < G) counts[i] = 0.0f;
}

__global__ void pool_nodes(const float* __restrict__ h, const int* __restrict__ batch,
                           float* __restrict__ pooled, float* __restrict__ counts, int n)
{
    int i = blockIdx.x * (blockDim.x >> 5) + (threadIdx.x >> 5);
    if (i >= n) return;
    int lane = threadIdx.x & 31;
    int g = batch[i];
    float4 v = *(const float4*)(h + (size_t)i * HD + (lane << 2));
    float* p = pooled + (size_t)g * HD + (lane << 2);
    asm volatile("red.global.add.v4.f32 [%0], {%1, %2, %3, %4};"
                 :: "l"(p), "f"(v.x), "f"(v.y), "f"(v.z), "f"(v.w) : "memory");
    if (lane == 0) atomicAdd(&counts[g], 1.0f);
}

// ---------------- final linear head --------------------------------------------
__global__ void final_linear(const float* __restrict__ pooled, const float* __restrict__ counts,
                             const float* __restrict__ linW, const float* __restrict__ linb,
                             float* __restrict__ out)
{
    int g = blockIdx.x;
    int c = threadIdx.x;
    float cntv = fmaxf(counts[g], 1.0f);
    float p = pooled[g * HD + c] / cntv;
    float v0 = p * linW[c * 2 + 0];
    float v1 = p * linW[c * 2 + 1];
#pragma unroll
    for (int o = 16; o > 0; o >>= 1) {
        v0 += __shfl_xor_sync(0xffffffffu, v0, o);
        v1 += __shfl_xor_sync(0xffffffffu, v1, o);
    }
    __shared__ float s0[4], s1[4];
    int w = threadIdx.x >> 5;
    if ((threadIdx.x & 31) == 0) { s0[w] = v0; s1[w] = v1; }
    __syncthreads();
    if (threadIdx.x == 0) {
        out[g * 2 + 0] = s0[0] + s0[1] + s0[2] + s0[3] + linb[0];
        out[g * 2 + 1] = s1[0] + s1[1] + s1[2] + s1[3] + linb[1];
    }
}

// ---------------- launch ---------------------------------------------------------
extern "C" void kernel_launch(void* const* d_in, const int* in_sizes, int n_in,
                              void* d_out, int out_size)
{
    const float* x     = (const float*)d_in[0];
    const int*   ei    = (const int*)d_in[1];
    const int*   batch = (const int*)d_in[2];
    const float* W[4]  = {(const float*)d_in[3], (const float*)d_in[5],
                          (const float*)d_in[7], (const float*)d_in[9]};
    const float* bv[4] = {(const float*)d_in[4], (const float*)d_in[6],
                          (const float*)d_in[8], (const float*)d_in[10]};
    const float* linW  = (const float*)d_in[11];
    const float* linb  = (const float*)d_in[12];
    float* out = (float*)d_out;

    const int n = in_sizes[0] / HD;
    const int E = in_sizes[1] / 2;
    const int G = out_size / 2;
    const int* src = ei;
    const int* dst = ei + E;

    float *buf0, *dinv, *pooled, *counts;
    __half* msg;
    int *ell, *cnt;
    __nv_bfloat16 *hi, *lo, *whi, *wlo;
    cudaGetSymbolAddress((void**)&buf0,   g_buf0);
    cudaGetSymbolAddress((void**)&msg,    g_msg);
    cudaGetSymbolAddress((void**)&hi,     g_hi);
    cudaGetSymbolAddress((void**)&lo,     g_lo);
    cudaGetSymbolAddress((void**)&whi,    g_whi);
    cudaGetSymbolAddress((void**)&wlo,    g_wlo);
    cudaGetSymbolAddress((void**)&ell,    g_ell);
    cudaGetSymbolAddress((void**)&cnt,    g_cnt);
    cudaGetSymbolAddress((void**)&dinv,   g_dinv);
    cudaGetSymbolAddress((void**)&pooled, g_pooled);
    cudaGetSymbolAddress((void**)&counts, g_counts);

    cudaFuncSetAttribute(gemm_hmma, cudaFuncAttributeMaxDynamicSharedMemorySize, S_TOT);

    // graph build + weight/input splits
    zero_cnt<<<(n + 255) / 256, 256>>>(cnt, n);
    fill_ell<<<(E + 255) / 256, 256>>>(src, dst, cnt, ell, E);
    make_dinv<<<(n + 255) / 256, 256>>>(cnt, dinv, n);
    wsplit4<<<(4 * HD * HD + 255) / 256, 256>>>(W[0], W[1], W[2], W[3], whi, wlo);
    xsplit<<<(n * HD + 255) / 256, 256>>>(x, hi, lo, n * HD);

    const int tiles = (n + 63) / 64;
    for (int l = 0; l < 4; l++) {
        gemm_hmma<<<tiles, 256, S_TOT>>>(hi, lo, whi + l * HD * HD, wlo + l * HD * HD,
                                         dinv, msg, n);
        gather_nodes<<<(n + 15) / 16, 256>>>(msg, ell, cnt, dinv, bv[l],
                                             hi, lo, buf0, (l == 3) ? 1 : 0, n);
    }

    zero_pool<<<(G * HD + 255) / 256, 256>>>(pooled, counts, G);
    pool_nodes<<<(n + 7) / 8, 256>>>(buf0, batch, pooled, counts, n);
    final_linear<<<G, 128>>>(pooled, counts, linW, linb, out);
}

// round 9
// speedup vs baseline: 1.4285x; 1.1828x over previous
#include <cuda_runtime.h>
#include <cuda_bf16.h>
#include <cuda_fp16.h>
#include <cstdint>
#include <cstddef>

#define HD   128
#define NMAX 100000
#define GMAX 1024
#define ELLW 64

// ---------------- scratch (device globals; no allocation allowed) ----------
__device__ __align__(256) float  g_buf0[NMAX * HD];           // h f32 (last layer)
__device__ __align__(256) __half g_msg[NMAX * HD];            // m' fp16 = (h @ W) * dinv[row]
__device__ __align__(256) __nv_bfloat16 g_h[NMAX * HD];       // h bf16 (GEMM A input)
__device__ __align__(256) __nv_bfloat16 g_whi[4 * HD * HD];   // W^T split hi ([N,K] row-major)
__device__ __align__(256) __nv_bfloat16 g_wlo[4 * HD * HD];   // W^T split lo
__device__ __align__(256) int   g_ell[NMAX * ELLW];
__device__ __align__(256) int   g_cnt[NMAX];
__device__ __align__(256) float g_dinv[NMAX];
__device__ __align__(256) float g_pooled[GMAX * HD];
__device__ __align__(256) float g_counts[GMAX];

// ---------------- helpers ----------------------------------------------------
__device__ __forceinline__ uint32_t smem_u32(const void* p) {
    uint32_t a;
    asm("{ .reg .u64 t; cvta.to.shared.u64 t, %1; cvt.u32.u64 %0, t; }" : "=r"(a) : "l"(p));
    return a;
}

__device__ __forceinline__ void ldm4(uint32_t* r, uint32_t addr) {
    asm volatile("ldmatrix.sync.aligned.m8n8.x4.shared.b16 {%0,%1,%2,%3}, [%4];"
                 : "=r"(r[0]), "=r"(r[1]), "=r"(r[2]), "=r"(r[3]) : "r"(addr));
}

__device__ __forceinline__ void mma_bf16(float* c, const uint32_t* a,
                                         uint32_t b0, uint32_t b1) {
    asm volatile(
        "mma.sync.aligned.m16n8k16.row.col.f32.bf16.bf16.f32 "
        "{%0,%1,%2,%3}, {%4,%5,%6,%7}, {%8,%9}, {%0,%1,%2,%3};"
        : "+f"(c[0]), "+f"(c[1]), "+f"(c[2]), "+f"(c[3])
        : "r"(a[0]), "r"(a[1]), "r"(a[2]), "r"(a[3]), "r"(b0), "r"(b1));
}

// SMEM plan: padded rows, stride 136 bf16 = 272 bytes (conflict-free ldmatrix)
#define ROWB 272
#define SA    0
#define SW_HI (SA + 64 * ROWB)
#define SW_LO (SW_HI + 128 * ROWB)
#define S_TOT (SW_LO + 128 * ROWB)

// ---------------- HMMA GEMM (2-pass bf16): M = fp16((A@(Whi+Wlo)) * dinv) ---
// A bf16 [n,128]; W^T bf16 hi/lo [128,128] ([N,K] row-major).
// block tile: 64m x 128n, 8 warps = 4 m-strips x 2 n-halves, full K=128.
__global__ __launch_bounds__(256, 2) void gemm_hmma(
    const __nv_bfloat16* __restrict__ A,
    const __nv_bfloat16* __restrict__ Whi, const __nv_bfloat16* __restrict__ Wlo,
    const float* __restrict__ dinv, __half* __restrict__ M, int n)
{
    extern __shared__ char smem[];
    const uint32_t sb = smem_u32(smem);
    const int tid = threadIdx.x;
    const int row0 = blockIdx.x * 64;

    // ---- load tiles ----
    const uint4 z4 = make_uint4(0, 0, 0, 0);
#pragma unroll
    for (int i = 0; i < 4; i++) {                    // A: 64 rows x 16 uint4
        int idx = tid + i * 256;
        int r = idx >> 4, c = idx & 15;
        int gr = row0 + r;
        uint4 v = z4;
        if (gr < n) v = *(const uint4*)(A + (size_t)gr * HD + c * 8);
        *(uint4*)(smem + SA + r * ROWB + c * 16) = v;
    }
#pragma unroll
    for (int i = 0; i < 8; i++) {                    // W hi+lo: 128 rows x 16 uint4 each
        int idx = tid + i * 256;
        int r = idx >> 4, c = idx & 15;
        *(uint4*)(smem + SW_HI + r * ROWB + c * 16) =
            *(const uint4*)(Whi + (size_t)r * HD + c * 8);
        *(uint4*)(smem + SW_LO + r * ROWB + c * 16) =
            *(const uint4*)(Wlo + (size_t)r * HD + c * 8);
    }
    __syncthreads();

    // ---- compute ----
    const int wid = tid >> 5, lane = tid & 31;
    const int mstrip = wid & 3;
    const int nhalf  = wid >> 2;
    const int lrow = lane & 15, lcol = lane >> 4;

    float acc[8][4];
#pragma unroll
    for (int p = 0; p < 8; p++)
#pragma unroll
        for (int j = 0; j < 4; j++) acc[p][j] = 0.0f;

    const uint32_t a0    = sb + SA    + (mstrip * 16 + lrow) * ROWB + lcol * 16;
    const uint32_t w_hi0 = sb + SW_HI + (nhalf * 64 + lrow) * ROWB + lcol * 16;
    const uint32_t w_lo0 = sb + SW_LO + (nhalf * 64 + lrow) * ROWB + lcol * 16;

#pragma unroll
    for (int ks = 0; ks < 8; ks++) {
        uint32_t a[4];
        ldm4(a, a0 + ks * 32);
#pragma unroll
        for (int p = 0; p < 4; p++) {
            uint32_t wh[4], wl[4];
            ldm4(wh, w_hi0 + p * (16 * ROWB) + ks * 32);
            mma_bf16(acc[2 * p],     a, wh[0], wh[2]);
            mma_bf16(acc[2 * p + 1], a, wh[1], wh[3]);
            ldm4(wl, w_lo0 + p * (16 * ROWB) + ks * 32);
            mma_bf16(acc[2 * p],     a, wl[0], wl[2]);
            mma_bf16(acc[2 * p + 1], a, wl[1], wl[3]);
        }
    }

    // ---- epilogue: scale by dinv[row], store fp16 ----
    const int rbase = row0 + mstrip * 16 + (lane >> 2);
    const int qc = (lane & 3) * 2;
#pragma unroll
    for (int rr = 0; rr < 2; rr++) {
        int row = rbase + rr * 8;
        if (row < n) {
            float w = dinv[row];
            __half* dst = M + (size_t)row * HD + nhalf * 64 + qc;
#pragma unroll
            for (int p = 0; p < 8; p++) {
                __half2 v = __floats2half2_rn(acc[p][rr * 2] * w, acc[p][rr * 2 + 1] * w);
                *(__half2*)(dst + p * 8) = v;
            }
        }
    }
}

// ---------------- graph build ------------------------------------------------
__global__ void zero_cnt(int* __restrict__ cnt, int n) {
    int i = blockIdx.x * blockDim.x + threadIdx.x;
    if (i < n) cnt[i] = 0;
}

__global__ void fill_ell(const int* __restrict__ src, const int* __restrict__ dst,
                         int* __restrict__ cnt, int* __restrict__ ell, int E)
{
    int e = blockIdx.x * blockDim.x + threadIdx.x;
    if (e >= E) return;
    int d = dst[e];
    int pos = atomicAdd(&cnt[d], 1);
    if (pos < ELLW) ell[(size_t)d * ELLW + pos] = src[e];
}

__global__ void make_dinv(const int* __restrict__ cnt, float* __restrict__ dinv, int n) {
    int i = blockIdx.x * blockDim.x + threadIdx.x;
    if (i < n) dinv[i] = rsqrtf((float)cnt[i] + 1.0f);
}

// ---------------- weight split + transpose (all 4 layers, one launch) -------
__global__ void wsplit4(const float* __restrict__ W0, const float* __restrict__ W1,
                        const float* __restrict__ W2, const float* __restrict__ W3,
                        __nv_bfloat16* __restrict__ Bhi, __nv_bfloat16* __restrict__ Blo)
{
    int idx = blockIdx.x * blockDim.x + threadIdx.x;
    if (idx >= 4 * HD * HD) return;
    int l = idx >> 14;
    int r = idx & (HD * HD - 1);
    const float* W = (l == 0) ? W0 : (l == 1) ? W1 : (l == 2) ? W2 : W3;
    int nn = r >> 7, kk = r & 127;
    float v = W[kk * HD + nn];
    __nv_bfloat16 hi = __float2bfloat16(v);
    __nv_bfloat16 lo = __float2bfloat16(v - __bfloat162float(hi));
    Bhi[idx] = hi;
    Blo[idx] = lo;
}

// ---------------- input convert ------------------------------------------------
__global__ void xtobf16(const float* __restrict__ x, __nv_bfloat16* __restrict__ h, int total) {
    int i = blockIdx.x * blockDim.x + threadIdx.x;
    if (i >= total) return;
    h[i] = __float2bfloat16(x[i]);
}

// ---------------- fused gather + selfloop + bias + relu ----------------------
// one warp per dst node, fp16 messages: lane covers 4 channels (8 bytes)  [R5-proven]
__global__ __launch_bounds__(256) void gather_nodes(
    const __half* __restrict__ m, const int* __restrict__ ell,
    const int* __restrict__ cnt, const float* __restrict__ dinv,
    const float* __restrict__ bias,
    __nv_bfloat16* __restrict__ out_h, float* __restrict__ out_f32, int mode, int n)
{
    int d = blockIdx.x * (blockDim.x >> 5) + (threadIdx.x >> 5);
    if (d >= n) return;
    const int lane = threadIdx.x & 31;
    const int c4 = lane << 2;

    // self term
    uint2 sraw = *(const uint2*)(m + (size_t)d * HD + c4);
    float2 s0 = __half22float2(*(const __half2*)&sraw.x);
    float2 s1 = __half22float2(*(const __half2*)&sraw.y);
    float a0 = s0.x, a1 = s0.y, a2 = s1.x, a3 = s1.y;

    const int deg = cnt[d];
    const int* row = ell + (size_t)d * ELLW;

    for (int base = 0; base < deg; base += 32) {
        int idx = (base + lane < deg) ? __ldg(row + base + lane) : 0;
        int lim = min(32, deg - base);
#pragma unroll 8
        for (int j = 0; j < lim; j++) {
            int s = __shfl_sync(0xffffffffu, idx, j);
            uint2 raw = *(const uint2*)(m + (size_t)s * HD + c4);
            float2 v0 = __half22float2(*(const __half2*)&raw.x);
            float2 v1 = __half22float2(*(const __half2*)&raw.y);
            a0 += v0.x; a1 += v0.y; a2 += v1.x; a3 += v1.y;
        }
    }

    float w = dinv[d];
    float4 bb = *(const float4*)(bias + c4);
    float o0 = fmaxf(fmaf(a0, w, bb.x), 0.f);
    float o1 = fmaxf(fmaf(a1, w, bb.y), 0.f);
    float o2 = fmaxf(fmaf(a2, w, bb.z), 0.f);
    float o3 = fmaxf(fmaf(a3, w, bb.w), 0.f);

    if (mode == 0) {
        __nv_bfloat162 h0 = {__float2bfloat16(o0), __float2bfloat16(o1)};
        __nv_bfloat162 h1 = {__float2bfloat16(o2), __float2bfloat16(o3)};
        *(__nv_bfloat162*)(out_h + (size_t)d * HD + c4)     = h0;
        *(__nv_bfloat162*)(out_h + (size_t)d * HD + c4 + 2) = h1;
    } else {
        *(float4*)(out_f32 + (size_t)d * HD + c4) = make_float4(o0, o1, o2, o3);
    }
}

// ---------------- pooling ------------------------------------------------------
__global__ void zero_pool(float* __restrict__ pooled, float* __restrict__ counts, int G) {
    int i = blockIdx.x * blockDim.x + threadIdx.x;
    if (i < G * HD) pooled[i] = 0.0f;
    if (i < G) counts[i] = 0.0f;
}

__global__ void pool_nodes(const float* __restrict__ h, const int* __restrict__ batch,
                           float* __restrict__ pooled, float* __restrict__ counts, int n)
{
    int i = blockIdx.x * (blockDim.x >> 5) + (threadIdx.x >> 5);
    if (i >= n) return;
    int lane = threadIdx.x & 31;
    int g = batch[i];
    float4 v = *(const float4*)(h + (size_t)i * HD + (lane << 2));
    float* p = pooled + (size_t)g * HD + (lane << 2);
    asm volatile("red.global.add.v4.f32 [%0], {%1, %2, %3, %4};"
                 :: "l"(p), "f"(v.x), "f"(v.y), "f"(v.z), "f"(v.w) : "memory");
    if (lane == 0) atomicAdd(&counts[g], 1.0f);
}

// ---------------- final linear head --------------------------------------------
__global__ void final_linear(const float* __restrict__ pooled, const float* __restrict__ counts,
                             const float* __restrict__ linW, const float* __restrict__ linb,
                             float* __restrict__ out)
{
    int g = blockIdx.x;
    int c = threadIdx.x;
    float cntv = fmaxf(counts[g], 1.0f);
    float p = pooled[g * HD + c] / cntv;
    float v0 = p * linW[c * 2 + 0];
    float v1 = p * linW[c * 2 + 1];
#pragma unroll
    for (int o = 16; o > 0; o >>= 1) {
        v0 += __shfl_xor_sync(0xffffffffu, v0, o);
        v1 += __shfl_xor_sync(0xffffffffu, v1, o);
    }
    __shared__ float s0[4], s1[4];
    int w = threadIdx.x >> 5;
    if ((threadIdx.x & 31) == 0) { s0[w] = v0; s1[w] = v1; }
    __syncthreads();
    if (threadIdx.x == 0) {
        out[g * 2 + 0] = s0[0] + s0[1] + s0[2] + s0[3] + linb[0];
        out[g * 2 + 1] = s1[0] + s1[1] + s1[2] + s1[3] + linb[1];
    }
}

// ---------------- launch ---------------------------------------------------------
extern "C" void kernel_launch(void* const* d_in, const int* in_sizes, int n_in,
                              void* d_out, int out_size)
{
    const float* x     = (const float*)d_in[0];
    const int*   ei    = (const int*)d_in[1];
    const int*   batch = (const int*)d_in[2];
    const float* W[4]  = {(const float*)d_in[3], (const float*)d_in[5],
                          (const float*)d_in[7], (const float*)d_in[9]};
    const float* bv[4] = {(const float*)d_in[4], (const float*)d_in[6],
                          (const float*)d_in[8], (const float*)d_in[10]};
    const float* linW  = (const float*)d_in[11];
    const float* linb  = (const float*)d_in[12];
    float* out = (float*)d_out;

    const int n = in_sizes[0] / HD;
    const int E = in_sizes[1] / 2;
    const int G = out_size / 2;
    const int* src = ei;
    const int* dst = ei + E;

    float *buf0, *dinv, *pooled, *counts;
    __half* msg;
    int *ell, *cnt;
    __nv_bfloat16 *hbuf, *whi, *wlo;
    cudaGetSymbolAddress((void**)&buf0,   g_buf0);
    cudaGetSymbolAddress((void**)&msg,    g_msg);
    cudaGetSymbolAddress((void**)&hbuf,   g_h);
    cudaGetSymbolAddress((void**)&whi,    g_whi);
    cudaGetSymbolAddress((void**)&wlo,    g_wlo);
    cudaGetSymbolAddress((void**)&ell,    g_ell);
    cudaGetSymbolAddress((void**)&cnt,    g_cnt);
    cudaGetSymbolAddress((void**)&dinv,   g_dinv);
    cudaGetSymbolAddress((void**)&pooled, g_pooled);
    cudaGetSymbolAddress((void**)&counts, g_counts);

    cudaFuncSetAttribute(gemm_hmma, cudaFuncAttributeMaxDynamicSharedMemorySize, S_TOT);

    // graph build + weight/input converts
    zero_cnt<<<(n + 255) / 256, 256>>>(cnt, n);
    fill_ell<<<(E + 255) / 256, 256>>>(src, dst, cnt, ell, E);
    make_dinv<<<(n + 255) / 256, 256>>>(cnt, dinv, n);
    wsplit4<<<(4 * HD * HD + 255) / 256, 256>>>(W[0], W[1], W[2], W[3], whi, wlo);
    xtobf16<<<(n * HD + 255) / 256, 256>>>(x, hbuf, n * HD);

    const int tiles = (n + 63) / 64;
    for (int l = 0; l < 4; l++) {
        gemm_hmma<<<tiles, 256, S_TOT>>>(hbuf, whi + l * HD * HD, wlo + l * HD * HD,
                                         dinv, msg, n);
        gather_nodes<<<(n + 7) / 8, 256>>>(msg, ell, cnt, dinv, bv[l],
                                           hbuf, buf0, (l == 3) ? 1 : 0, n);
    }

    zero_pool<<<(G * HD + 255) / 256, 256>>>(pooled, counts, G);
    pool_nodes<<<(n + 7) / 8, 256>>>(buf0, batch, pooled, counts, n);
    final_linear<<<G, 128>>>(pooled, counts, linW, linb, out);
}

// round 10
// speedup vs baseline: 1.4936x; 1.0456x over previous
#include <cuda_runtime.h>
#include <cuda_bf16.h>
#include <cuda_fp16.h>
#include <cstdint>
#include <cstddef>

#define HD   128
#define NMAX 100000
#define GMAX 1024
#define ELLW 64

// ---------------- scratch (device globals; no allocation allowed) ----------
__device__ __align__(256) __half g_msg[NMAX * HD];            // m' fp16 = (h @ W) * dinv[row]
__device__ __align__(256) __nv_bfloat16 g_h[NMAX * HD];       // h bf16 (GEMM A input)
__device__ __align__(256) __nv_bfloat16 g_whi[4 * HD * HD];   // W^T split hi ([N,K] row-major)
__device__ __align__(256) __nv_bfloat16 g_wlo[4 * HD * HD];   // W^T split lo
__device__ __align__(256) int   g_ell[NMAX * ELLW];
__device__ __align__(256) int   g_cnt[NMAX];
__device__ __align__(256) float g_dinv[NMAX];
__device__ __align__(256) float g_pooled[GMAX * HD];
__device__ __align__(256) float g_counts[GMAX];

// ---------------- helpers ----------------------------------------------------
__device__ __forceinline__ uint32_t smem_u32(const void* p) {
    uint32_t a;
    asm("{ .reg .u64 t; cvta.to.shared.u64 t, %1; cvt.u32.u64 %0, t; }" : "=r"(a) : "l"(p));
    return a;
}

__device__ __forceinline__ void ldm4(uint32_t* r, uint32_t addr) {
    asm volatile("ldmatrix.sync.aligned.m8n8.x4.shared.b16 {%0,%1,%2,%3}, [%4];"
                 : "=r"(r[0]), "=r"(r[1]), "=r"(r[2]), "=r"(r[3]) : "r"(addr));
}

__device__ __forceinline__ void mma_bf16(float* c, const uint32_t* a,
                                         uint32_t b0, uint32_t b1) {
    asm volatile(
        "mma.sync.aligned.m16n8k16.row.col.f32.bf16.bf16.f32 "
        "{%0,%1,%2,%3}, {%4,%5,%6,%7}, {%8,%9}, {%0,%1,%2,%3};"
        : "+f"(c[0]), "+f"(c[1]), "+f"(c[2]), "+f"(c[3])
        : "r"(a[0]), "r"(a[1]), "r"(a[2]), "r"(a[3]), "r"(b0), "r"(b1));
}

// SMEM plan: padded rows, stride 136 bf16 = 272 bytes (conflict-free ldmatrix)
#define ROWB 272
#define SA    0
#define SW_HI (SA + 64 * ROWB)
#define SW_LO (SW_HI + 128 * ROWB)
#define S_TOT (SW_LO + 128 * ROWB)

// ---------------- HMMA GEMM (2-pass bf16): M = fp16((A@(Whi+Wlo)) * dinv) ---
// [R9-proven] A bf16 [n,128]; W^T bf16 hi/lo [128,128] ([N,K] row-major).
__global__ __launch_bounds__(256, 2) void gemm_hmma(
    const __nv_bfloat16* __restrict__ A,
    const __nv_bfloat16* __restrict__ Whi, const __nv_bfloat16* __restrict__ Wlo,
    const float* __restrict__ dinv, __half* __restrict__ M, int n)
{
    extern __shared__ char smem[];
    const uint32_t sb = smem_u32(smem);
    const int tid = threadIdx.x;
    const int row0 = blockIdx.x * 64;

    const uint4 z4 = make_uint4(0, 0, 0, 0);
#pragma unroll
    for (int i = 0; i < 4; i++) {                    // A: 64 rows x 16 uint4
        int idx = tid + i * 256;
        int r = idx >> 4, c = idx & 15;
        int gr = row0 + r;
        uint4 v = z4;
        if (gr < n) v = *(const uint4*)(A + (size_t)gr * HD + c * 8);
        *(uint4*)(smem + SA + r * ROWB + c * 16) = v;
    }
#pragma unroll
    for (int i = 0; i < 8; i++) {                    // W hi+lo: 128 rows x 16 uint4 each
        int idx = tid + i * 256;
        int r = idx >> 4, c = idx & 15;
        *(uint4*)(smem + SW_HI + r * ROWB + c * 16) =
            *(const uint4*)(Whi + (size_t)r * HD + c * 8);
        *(uint4*)(smem + SW_LO + r * ROWB + c * 16) =
            *(const uint4*)(Wlo + (size_t)r * HD + c * 8);
    }
    __syncthreads();

    const int wid = tid >> 5, lane = tid & 31;
    const int mstrip = wid & 3;
    const int nhalf  = wid >> 2;
    const int lrow = lane & 15, lcol = lane >> 4;

    float acc[8][4];
#pragma unroll
    for (int p = 0; p < 8; p++)
#pragma unroll
        for (int j = 0; j < 4; j++) acc[p][j] = 0.0f;

    const uint32_t a0    = sb + SA    + (mstrip * 16 + lrow) * ROWB + lcol * 16;
    const uint32_t w_hi0 = sb + SW_HI + (nhalf * 64 + lrow) * ROWB + lcol * 16;
    const uint32_t w_lo0 = sb + SW_LO + (nhalf * 64 + lrow) * ROWB + lcol * 16;

#pragma unroll
    for (int ks = 0; ks < 8; ks++) {
        uint32_t a[4];
        ldm4(a, a0 + ks * 32);
#pragma unroll
        for (int p = 0; p < 4; p++) {
            uint32_t wh[4], wl[4];
            ldm4(wh, w_hi0 + p * (16 * ROWB) + ks * 32);
            mma_bf16(acc[2 * p],     a, wh[0], wh[2]);
            mma_bf16(acc[2 * p + 1], a, wh[1], wh[3]);
            ldm4(wl, w_lo0 + p * (16 * ROWB) + ks * 32);
            mma_bf16(acc[2 * p],     a, wl[0], wl[2]);
            mma_bf16(acc[2 * p + 1], a, wl[1], wl[3]);
        }
    }

    const int rbase = row0 + mstrip * 16 + (lane >> 2);
    const int qc = (lane & 3) * 2;
#pragma unroll
    for (int rr = 0; rr < 2; rr++) {
        int row = rbase + rr * 8;
        if (row < n) {
            float w = dinv[row];
            __half* dst = M + (size_t)row * HD + nhalf * 64 + qc;
#pragma unroll
            for (int p = 0; p < 8; p++) {
                __half2 v = __floats2half2_rn(acc[p][rr * 2] * w, acc[p][rr * 2 + 1] * w);
                *(__half2*)(dst + p * 8) = v;
            }
        }
    }
}

// ---------------- setup: zero cnt + zero pooled + batch histogram -----------
__global__ void prep(int* __restrict__ cnt, float* __restrict__ pooled,
                     float* __restrict__ counts, const int* __restrict__ batch,
                     int n, int G)
{
    int i = blockIdx.x * blockDim.x + threadIdx.x;
    if (i < n) cnt[i] = 0;
    if (i < G * HD) pooled[i] = 0.0f;
    if (i < G) counts[i] = 0.0f;
    // batch histogram (after counts zeroed by lower indices? no: separate grid pass)
}

__global__ void batch_hist(const int* __restrict__ batch, float* __restrict__ counts, int n) {
    int i = blockIdx.x * blockDim.x + threadIdx.x;
    if (i < n) atomicAdd(&counts[batch[i]], 1.0f);
}

__global__ void fill_ell(const int* __restrict__ src, const int* __restrict__ dst,
                         int* __restrict__ cnt, int* __restrict__ ell, int E)
{
    int e = blockIdx.x * blockDim.x + threadIdx.x;
    if (e >= E) return;
    int d = dst[e];
    int pos = atomicAdd(&cnt[d], 1);
    if (pos < ELLW) ell[(size_t)d * ELLW + pos] = src[e];
}

__global__ void make_dinv(const int* __restrict__ cnt, float* __restrict__ dinv, int n) {
    int i = blockIdx.x * blockDim.x + threadIdx.x;
    if (i < n) dinv[i] = rsqrtf((float)cnt[i] + 1.0f);
}

// ---------------- weight split + transpose (all 4 layers, one launch) -------
__global__ void wsplit4(const float* __restrict__ W0, const float* __restrict__ W1,
                        const float* __restrict__ W2, const float* __restrict__ W3,
                        __nv_bfloat16* __restrict__ Bhi, __nv_bfloat16* __restrict__ Blo)
{
    int idx = blockIdx.x * blockDim.x + threadIdx.x;
    if (idx >= 4 * HD * HD) return;
    int l = idx >> 14;
    int r = idx & (HD * HD - 1);
    const float* W = (l == 0) ? W0 : (l == 1) ? W1 : (l == 2) ? W2 : W3;
    int nn = r >> 7, kk = r & 127;
    float v = W[kk * HD + nn];
    __nv_bfloat16 hi = __float2bfloat16(v);
    __nv_bfloat16 lo = __float2bfloat16(v - __bfloat162float(hi));
    Bhi[idx] = hi;
    Blo[idx] = lo;
}

// ---------------- input convert ------------------------------------------------
__global__ void xtobf16(const float* __restrict__ x, __nv_bfloat16* __restrict__ h, int total) {
    int i = blockIdx.x * blockDim.x + threadIdx.x;
    if (i >= total) return;
    h[i] = __float2bfloat16(x[i]);
}

// ---------------- fused gather + selfloop + bias + relu (+ pool on last) ----
// one warp per dst node, fp16 messages: lane covers 4 channels (8 bytes)
// mode 0: write h bf16.  mode 1 (last layer): red.global.add into pooled[batch[d]].
__global__ __launch_bounds__(256) void gather_nodes(
    const __half* __restrict__ m, const int* __restrict__ ell,
    const int* __restrict__ cnt, const float* __restrict__ dinv,
    const float* __restrict__ bias,
    __nv_bfloat16* __restrict__ out_h,
    const int* __restrict__ batch, float* __restrict__ pooled,
    int mode, int n)
{
    int d = blockIdx.x * (blockDim.x >> 5) + (threadIdx.x >> 5);
    if (d >= n) return;
    const int lane = threadIdx.x & 31;
    const int c4 = lane << 2;

    // self term
    uint2 sraw = *(const uint2*)(m + (size_t)d * HD + c4);
    float2 s0 = __half22float2(*(const __half2*)&sraw.x);
    float2 s1 = __half22float2(*(const __half2*)&sraw.y);
    float a0 = s0.x, a1 = s0.y, a2 = s1.x, a3 = s1.y;

    const int deg = cnt[d];
    const int* row = ell + (size_t)d * ELLW;

    for (int base = 0; base < deg; base += 32) {
        int idx = (base + lane < deg) ? __ldg(row + base + lane) : 0;
        int lim = min(32, deg - base);
#pragma unroll 8
        for (int j = 0; j < lim; j++) {
            int s = __shfl_sync(0xffffffffu, idx, j);
            uint2 raw = *(const uint2*)(m + (size_t)s * HD + c4);
            float2 v0 = __half22float2(*(const __half2*)&raw.x);
            float2 v1 = __half22float2(*(const __half2*)&raw.y);
            a0 += v0.x; a1 += v0.y; a2 += v1.x; a3 += v1.y;
        }
    }

    float w = dinv[d];
    float4 bb = *(const float4*)(bias + c4);
    float o0 = fmaxf(fmaf(a0, w, bb.x), 0.f);
    float o1 = fmaxf(fmaf(a1, w, bb.y), 0.f);
    float o2 = fmaxf(fmaf(a2, w, bb.z), 0.f);
    float o3 = fmaxf(fmaf(a3, w, bb.w), 0.f);

    if (mode == 0) {
        __nv_bfloat162 h0 = {__float2bfloat16(o0), __float2bfloat16(o1)};
        __nv_bfloat162 h1 = {__float2bfloat16(o2), __float2bfloat16(o3)};
        *(__nv_bfloat162*)(out_h + (size_t)d * HD + c4)     = h0;
        *(__nv_bfloat162*)(out_h + (size_t)d * HD + c4 + 2) = h1;
    } else {
        int g = batch[d];
        float* p = pooled + (size_t)g * HD + c4;
        asm volatile("red.global.add.v4.f32 [%0], {%1, %2, %3, %4};"
                     :: "l"(p), "f"(o0), "f"(o1), "f"(o2), "f"(o3) : "memory");
    }
}

// ---------------- final linear head --------------------------------------------
__global__ void final_linear(const float* __restrict__ pooled, const float* __restrict__ counts,
                             const float* __restrict__ linW, const float* __restrict__ linb,
                             float* __restrict__ out)
{
    int g = blockIdx.x;
    int c = threadIdx.x;
    float cntv = fmaxf(counts[g], 1.0f);
    float p = pooled[g * HD + c] / cntv;
    float v0 = p * linW[c * 2 + 0];
    float v1 = p * linW[c * 2 + 1];
#pragma unroll
    for (int o = 16; o > 0; o >>= 1) {
        v0 += __shfl_xor_sync(0xffffffffu, v0, o);
        v1 += __shfl_xor_sync(0xffffffffu, v1, o);
    }
    __shared__ float s0[4], s1[4];
    int w = threadIdx.x >> 5;
    if ((threadIdx.x & 31) == 0) { s0[w] = v0; s1[w] = v1; }
    __syncthreads();
    if (threadIdx.x == 0) {
        out[g * 2 + 0] = s0[0] + s0[1] + s0[2] + s0[3] + linb[0];
        out[g * 2 + 1] = s1[0] + s1[1] + s1[2] + s1[3] + linb[1];
    }
}

// ---------------- launch ---------------------------------------------------------
extern "C" void kernel_launch(void* const* d_in, const int* in_sizes, int n_in,
                              void* d_out, int out_size)
{
    const float* x     = (const float*)d_in[0];
    const int*   ei    = (const int*)d_in[1];
    const int*   batch = (const int*)d_in[2];
    const float* W[4]  = {(const float*)d_in[3], (const float*)d_in[5],
                          (const float*)d_in[7], (const float*)d_in[9]};
    const float* bv[4] = {(const float*)d_in[4], (const float*)d_in[6],
                          (const float*)d_in[8], (const float*)d_in[10]};
    const float* linW  = (const float*)d_in[11];
    const float* linb  = (const float*)d_in[12];
    float* out = (float*)d_out;

    const int n = in_sizes[0] / HD;
    const int E = in_sizes[1] / 2;
    const int G = out_size / 2;
    const int* src = ei;
    const int* dst = ei + E;

    float *dinv, *pooled, *counts;
    __half* msg;
    int *ell, *cnt;
    __nv_bfloat16 *hbuf, *whi, *wlo;
    cudaGetSymbolAddress((void**)&msg,    g_msg);
    cudaGetSymbolAddress((void**)&hbuf,   g_h);
    cudaGetSymbolAddress((void**)&whi,    g_whi);
    cudaGetSymbolAddress((void**)&wlo,    g_wlo);
    cudaGetSymbolAddress((void**)&ell,    g_ell);
    cudaGetSymbolAddress((void**)&cnt,    g_cnt);
    cudaGetSymbolAddress((void**)&dinv,   g_dinv);
    cudaGetSymbolAddress((void**)&pooled, g_pooled);
    cudaGetSymbolAddress((void**)&counts, g_counts);

    cudaFuncSetAttribute(gemm_hmma, cudaFuncAttributeMaxDynamicSharedMemorySize, S_TOT);

    // setup: zero buffers, batch histogram, ELL build, converts
    const int prep_n = (n > G * HD) ? n : G * HD;
    prep<<<(prep_n + 255) / 256, 256>>>(cnt, pooled, counts, batch, n, G);
    batch_hist<<<(n + 255) / 256, 256>>>(batch, counts, n);
    fill_ell<<<(E + 255) / 256, 256>>>(src, dst, cnt, ell, E);
    make_dinv<<<(n + 255) / 256, 256>>>(cnt, dinv, n);
    wsplit4<<<(4 * HD * HD + 255) / 256, 256>>>(W[0], W[1], W[2], W[3], whi, wlo);
    xtobf16<<<(n * HD + 255) / 256, 256>>>(x, hbuf, n * HD);

    const int tiles = (n + 63) / 64;
    for (int l = 0; l < 4; l++) {
        gemm_hmma<<<tiles, 256, S_TOT>>>(hbuf, whi + l * HD * HD, wlo + l * HD * HD,
                                         dinv, msg, n);
        gather_nodes<<<(n + 7) / 8, 256>>>(msg, ell, cnt, dinv, bv[l],
                                           hbuf, batch, pooled, (l == 3) ? 1 : 0, n);
    }

    final_linear<<<G, 128>>>(pooled, counts, linW, linb, out);
}

// round 11
// speedup vs baseline: 1.7029x; 1.1402x over previous
#include <cuda_runtime.h>
#include <cuda_bf16.h>
#include <cuda_fp16.h>
#include <cstdint>
#include <cstddef>

#define HD   128
#define NMAX 100000
#define GMAX 1024
#define ELLW 64

// ---------------- scratch (device globals; no allocation allowed) ----------
__device__ __align__(256) __half g_msg[NMAX * HD];            // m' fp16 = (h @ W) * dinv[row]
__device__ __align__(256) __nv_bfloat16 g_h[NMAX * HD];       // h bf16 (GEMM A input)
__device__ __align__(256) __nv_bfloat16 g_whi[4 * HD * HD];   // W^T split hi ([N,K] row-major)
__device__ __align__(256) __nv_bfloat16 g_wlo[4 * HD * HD];   // W^T split lo
__device__ __align__(256) int   g_ell[NMAX * ELLW];
__device__ __align__(256) int   g_cnt[NMAX];
__device__ __align__(256) float g_dinv[NMAX];
__device__ __align__(256) float g_pooled[GMAX * HD];
__device__ __align__(256) float g_counts[GMAX];

// ---------------- helpers ----------------------------------------------------
__device__ __forceinline__ uint32_t smem_u32(const void* p) {
    uint32_t a;
    asm("{ .reg .u64 t; cvta.to.shared.u64 t, %1; cvt.u32.u64 %0, t; }" : "=r"(a) : "l"(p));
    return a;
}

__device__ __forceinline__ void ldm4(uint32_t* r, uint32_t addr) {
    asm volatile("ldmatrix.sync.aligned.m8n8.x4.shared.b16 {%0,%1,%2,%3}, [%4];"
                 : "=r"(r[0]), "=r"(r[1]), "=r"(r[2]), "=r"(r[3]) : "r"(addr));
}

__device__ __forceinline__ void mma_bf16(float* c, const uint32_t* a,
                                         uint32_t b0, uint32_t b1) {
    asm volatile(
        "mma.sync.aligned.m16n8k16.row.col.f32.bf16.bf16.f32 "
        "{%0,%1,%2,%3}, {%4,%5,%6,%7}, {%8,%9}, {%0,%1,%2,%3};"
        : "+f"(c[0]), "+f"(c[1]), "+f"(c[2]), "+f"(c[3])
        : "r"(a[0]), "r"(a[1]), "r"(a[2]), "r"(a[3]), "r"(b0), "r"(b1));
}

__device__ __forceinline__ uint32_t pack_bf16x2(float x, float y) {
    __nv_bfloat162 b = {__float2bfloat16(x), __float2bfloat16(y)};
    return *(uint32_t*)&b;
}

// SMEM plan: padded rows, stride 136 bf16 = 272 bytes (conflict-free ldmatrix)
#define ROWB 272
#define SA    0
#define SW_HI (SA + 64 * ROWB)
#define SW_LO (SW_HI + 128 * ROWB)
#define S_TOT (SW_LO + 128 * ROWB)

#define GEMM_CTAS 296   // 2 per SM, persistent

// ---------------- persistent HMMA GEMM (2-pass bf16) -------------------------
// W hi/lo loaded into SMEM ONCE, then grid-stride over m-tiles.
// If xf != nullptr (layer 0), A is read from f32 x and converted in the fill.
__global__ __launch_bounds__(256, 2) void gemm_hmma(
    const __nv_bfloat16* __restrict__ A, const float* __restrict__ xf,
    const __nv_bfloat16* __restrict__ Whi, const __nv_bfloat16* __restrict__ Wlo,
    const float* __restrict__ dinv, __half* __restrict__ M, int n, int ntiles)
{
    extern __shared__ char smem[];
    const uint32_t sb = smem_u32(smem);
    const int tid = threadIdx.x;

    // ---- load W tiles once ----
#pragma unroll
    for (int i = 0; i < 8; i++) {                    // 128 rows x 16 uint4 each
        int idx = tid + i * 256;
        int r = idx >> 4, c = idx & 15;
        *(uint4*)(smem + SW_HI + r * ROWB + c * 16) =
            *(const uint4*)(Whi + (size_t)r * HD + c * 8);
        *(uint4*)(smem + SW_LO + r * ROWB + c * 16) =
            *(const uint4*)(Wlo + (size_t)r * HD + c * 8);
    }

    const int wid = tid >> 5, lane = tid & 31;
    const int mstrip = wid & 3;
    const int nhalf  = wid >> 2;
    const int lrow = lane & 15, lcol = lane >> 4;

    const uint32_t a0    = sb + SA    + (mstrip * 16 + lrow) * ROWB + lcol * 16;
    const uint32_t w_hi0 = sb + SW_HI + (nhalf * 64 + lrow) * ROWB + lcol * 16;
    const uint32_t w_lo0 = sb + SW_LO + (nhalf * 64 + lrow) * ROWB + lcol * 16;
    const uint4 z4 = make_uint4(0, 0, 0, 0);

    for (int tile = blockIdx.x; tile < ntiles; tile += GEMM_CTAS) {
        const int row0 = tile * 64;

        // ---- fill A tile: 64 rows x 16 uint4 ----
#pragma unroll
        for (int i = 0; i < 4; i++) {
            int idx = tid + i * 256;
            int r = idx >> 4, c = idx & 15;
            int gr = row0 + r;
            uint4 v = z4;
            if (gr < n) {
                if (xf) {
                    const float* srcp = xf + (size_t)gr * HD + c * 8;
                    float4 f0 = *(const float4*)(srcp);
                    float4 f1 = *(const float4*)(srcp + 4);
                    v.x = pack_bf16x2(f0.x, f0.y);
                    v.y = pack_bf16x2(f0.z, f0.w);
                    v.z = pack_bf16x2(f1.x, f1.y);
                    v.w = pack_bf16x2(f1.z, f1.w);
                } else {
                    v = *(const uint4*)(A + (size_t)gr * HD + c * 8);
                }
            }
            *(uint4*)(smem + SA + r * ROWB + c * 16) = v;
        }
        __syncthreads();

        // ---- compute ----
        float acc[8][4];
#pragma unroll
        for (int p = 0; p < 8; p++)
#pragma unroll
            for (int j = 0; j < 4; j++) acc[p][j] = 0.0f;

#pragma unroll
        for (int ks = 0; ks < 8; ks++) {
            uint32_t a[4];
            ldm4(a, a0 + ks * 32);
#pragma unroll
            for (int p = 0; p < 4; p++) {
                uint32_t wh[4], wl[4];
                ldm4(wh, w_hi0 + p * (16 * ROWB) + ks * 32);
                mma_bf16(acc[2 * p],     a, wh[0], wh[2]);
                mma_bf16(acc[2 * p + 1], a, wh[1], wh[3]);
                ldm4(wl, w_lo0 + p * (16 * ROWB) + ks * 32);
                mma_bf16(acc[2 * p],     a, wl[0], wl[2]);
                mma_bf16(acc[2 * p + 1], a, wl[1], wl[3]);
            }
        }

        // ---- epilogue: scale by dinv[row], store fp16 ----
        const int rbase = row0 + mstrip * 16 + (lane >> 2);
        const int qc = (lane & 3) * 2;
#pragma unroll
        for (int rr = 0; rr < 2; rr++) {
            int row = rbase + rr * 8;
            if (row < n) {
                float w = dinv[row];
                __half* dst = M + (size_t)row * HD + nhalf * 64 + qc;
#pragma unroll
                for (int p = 0; p < 8; p++) {
                    __half2 v = __floats2half2_rn(acc[p][rr * 2] * w, acc[p][rr * 2 + 1] * w);
                    *(__half2*)(dst + p * 8) = v;
                }
            }
        }
        __syncthreads();   // A tile reuse barrier
    }
}

// ---------------- setup: zero cnt + zero pooled + zero counts ----------------
__global__ void prep(int* __restrict__ cnt, float* __restrict__ pooled,
                     float* __restrict__ counts, int n, int G)
{
    int i = blockIdx.x * blockDim.x + threadIdx.x;
    if (i < n) cnt[i] = 0;
    if (i < G * HD) pooled[i] = 0.0f;
    if (i < G) counts[i] = 0.0f;
}

__global__ void batch_hist(const int* __restrict__ batch, float* __restrict__ counts, int n) {
    int i = blockIdx.x * blockDim.x + threadIdx.x;
    if (i < n) atomicAdd(&counts[batch[i]], 1.0f);
}

__global__ void fill_ell(const int* __restrict__ src, const int* __restrict__ dst,
                         int* __restrict__ cnt, int* __restrict__ ell, int E)
{
    int e = blockIdx.x * blockDim.x + threadIdx.x;
    if (e >= E) return;
    int d = dst[e];
    int pos = atomicAdd(&cnt[d], 1);
    if (pos < ELLW) ell[(size_t)d * ELLW + pos] = src[e];
}

__global__ void make_dinv(const int* __restrict__ cnt, float* __restrict__ dinv, int n) {
    int i = blockIdx.x * blockDim.x + threadIdx.x;
    if (i < n) dinv[i] = rsqrtf((float)cnt[i] + 1.0f);
}

// ---------------- weight split + transpose (all 4 layers, one launch) -------
__global__ void wsplit4(const float* __restrict__ W0, const float* __restrict__ W1,
                        const float* __restrict__ W2, const float* __restrict__ W3,
                        __nv_bfloat16* __restrict__ Bhi, __nv_bfloat16* __restrict__ Blo)
{
    int idx = blockIdx.x * blockDim.x + threadIdx.x;
    if (idx >= 4 * HD * HD) return;
    int l = idx >> 14;
    int r = idx & (HD * HD - 1);
    const float* W = (l == 0) ? W0 : (l == 1) ? W1 : (l == 2) ? W2 : W3;
    int nn = r >> 7, kk = r & 127;
    float v = W[kk * HD + nn];
    __nv_bfloat16 hi = __float2bfloat16(v);
    __nv_bfloat16 lo = __float2bfloat16(v - __bfloat162float(hi));
    Bhi[idx] = hi;
    Blo[idx] = lo;
}

// ---------------- fused gather + selfloop + bias + relu (+ pool on last) ----
// one warp per dst node, fp16 messages: lane covers 4 channels (8 bytes)
__global__ __launch_bounds__(256) void gather_nodes(
    const __half* __restrict__ m, const int* __restrict__ ell,
    const int* __restrict__ cnt, const float* __restrict__ dinv,
    const float* __restrict__ bias,
    __nv_bfloat16* __restrict__ out_h,
    const int* __restrict__ batch, float* __restrict__ pooled,
    int mode, int n)
{
    int d = blockIdx.x * (blockDim.x >> 5) + (threadIdx.x >> 5);
    if (d >= n) return;
    const int lane = threadIdx.x & 31;
    const int c4 = lane << 2;

    // self term
    uint2 sraw = *(const uint2*)(m + (size_t)d * HD + c4);
    float2 s0 = __half22float2(*(const __half2*)&sraw.x);
    float2 s1 = __half22float2(*(const __half2*)&sraw.y);
    float a0 = s0.x, a1 = s0.y, a2 = s1.x, a3 = s1.y;

    const int deg = cnt[d];
    const int* row = ell + (size_t)d * ELLW;

    for (int base = 0; base < deg; base += 32) {
        int idx = (base + lane < deg) ? __ldg(row + base + lane) : 0;
        int lim = min(32, deg - base);
#pragma unroll 8
        for (int j = 0; j < lim; j++) {
            int s = __shfl_sync(0xffffffffu, idx, j);
            uint2 raw = *(const uint2*)(m + (size_t)s * HD + c4);
            float2 v0 = __half22float2(*(const __half2*)&raw.x);
            float2 v1 = __half22float2(*(const __half2*)&raw.y);
            a0 += v0.x; a1 += v0.y; a2 += v1.x; a3 += v1.y;
        }
    }

    float w = dinv[d];
    float4 bb = *(const float4*)(bias + c4);
    float o0 = fmaxf(fmaf(a0, w, bb.x), 0.f);
    float o1 = fmaxf(fmaf(a1, w, bb.y), 0.f);
    float o2 = fmaxf(fmaf(a2, w, bb.z), 0.f);
    float o3 = fmaxf(fmaf(a3, w, bb.w), 0.f);

    if (mode == 0) {
        __nv_bfloat162 h0 = {__float2bfloat16(o0), __float2bfloat16(o1)};
        __nv_bfloat162 h1 = {__float2bfloat16(o2), __float2bfloat16(o3)};
        *(__nv_bfloat162*)(out_h + (size_t)d * HD + c4)     = h0;
        *(__nv_bfloat162*)(out_h + (size_t)d * HD + c4 + 2) = h1;
    } else {
        int g = batch[d];
        float* p = pooled + (size_t)g * HD + c4;
        asm volatile("red.global.add.v4.f32 [%0], {%1, %2, %3, %4};"
                     :: "l"(p), "f"(o0), "f"(o1), "f"(o2), "f"(o3) : "memory");
    }
}

// ---------------- final linear head --------------------------------------------
__global__ void final_linear(const float* __restrict__ pooled, const float* __restrict__ counts,
                             const float* __restrict__ linW, const float* __restrict__ linb,
                             float* __restrict__ out)
{
    int g = blockIdx.x;
    int c = threadIdx.x;
    float cntv = fmaxf(counts[g], 1.0f);
    float p = pooled[g * HD + c] / cntv;
    float v0 = p * linW[c * 2 + 0];
    float v1 = p * linW[c * 2 + 1];
#pragma unroll
    for (int o = 16; o > 0; o >>= 1) {
        v0 += __shfl_xor_sync(0xffffffffu, v0, o);
        v1 += __shfl_xor_sync(0xffffffffu, v1, o);
    }
    __shared__ float s0[4], s1[4];
    int w = threadIdx.x >> 5;
    if ((threadIdx.x & 31) == 0) { s0[w] = v0; s1[w] = v1; }
    __syncthreads();
    if (threadIdx.x == 0) {
        out[g * 2 + 0] = s0[0] + s0[1] + s0[2] + s0[3] + linb[0];
        out[g * 2 + 1] = s1[0] + s1[1] + s1[2] + s1[3] + linb[1];
    }
}

// ---------------- launch ---------------------------------------------------------
extern "C" void kernel_launch(void* const* d_in, const int* in_sizes, int n_in,
                              void* d_out, int out_size)
{
    const float* x     = (const float*)d_in[0];
    const int*   ei    = (const int*)d_in[1];
    const int*   batch = (const int*)d_in[2];
    const float* W[4]  = {(const float*)d_in[3], (const float*)d_in[5],
                          (const float*)d_in[7], (const float*)d_in[9]};
    const float* bv[4] = {(const float*)d_in[4], (const float*)d_in[6],
                          (const float*)d_in[8], (const float*)d_in[10]};
    const float* linW  = (const float*)d_in[11];
    const float* linb  = (const float*)d_in[12];
    float* out = (float*)d_out;

    const int n = in_sizes[0] / HD;
    const int E = in_sizes[1] / 2;
    const int G = out_size / 2;
    const int* src = ei;
    const int* dst = ei + E;

    float *dinv, *pooled, *counts;
    __half* msg;
    int *ell, *cnt;
    __nv_bfloat16 *hbuf, *whi, *wlo;
    cudaGetSymbolAddress((void**)&msg,    g_msg);
    cudaGetSymbolAddress((void**)&hbuf,   g_h);
    cudaGetSymbolAddress((void**)&whi,    g_whi);
    cudaGetSymbolAddress((void**)&wlo,    g_wlo);
    cudaGetSymbolAddress((void**)&ell,    g_ell);
    cudaGetSymbolAddress((void**)&cnt,    g_cnt);
    cudaGetSymbolAddress((void**)&dinv,   g_dinv);
    cudaGetSymbolAddress((void**)&pooled, g_pooled);
    cudaGetSymbolAddress((void**)&counts, g_counts);

    cudaFuncSetAttribute(gemm_hmma, cudaFuncAttributeMaxDynamicSharedMemorySize, S_TOT);

    // setup: zero buffers, batch histogram, ELL build, weight split
    const int prep_n = (n > G * HD) ? n : G * HD;
    prep<<<(prep_n + 255) / 256, 256>>>(cnt, pooled, counts, n, G);
    batch_hist<<<(n + 255) / 256, 256>>>(batch, counts, n);
    fill_ell<<<(E + 255) / 256, 256>>>(src, dst, cnt, ell, E);
    make_dinv<<<(n + 255) / 256, 256>>>(cnt, dinv, n);
    wsplit4<<<(4 * HD * HD + 255) / 256, 256>>>(W[0], W[1], W[2], W[3], whi, wlo);

    const int ntiles = (n + 63) / 64;
    for (int l = 0; l < 4; l++) {
        gemm_hmma<<<GEMM_CTAS, 256, S_TOT>>>(hbuf, (l == 0) ? x : nullptr,
                                             whi + l * HD * HD, wlo + l * HD * HD,
                                             dinv, msg, n, ntiles);
        gather_nodes<<<(n + 7) / 8, 256>>>(msg, ell, cnt, dinv, bv[l],
                                           hbuf, batch, pooled, (l == 3) ? 1 : 0, n);
    }

    final_linear<<<G, 128>>>(pooled, counts, linW, linb, out);
}

// round 12
// speedup vs baseline: 1.7862x; 1.0489x over previous
#include <cuda_runtime.h>
#include <cuda_bf16.h>
#include <cuda_fp16.h>
#include <cstdint>
#include <cstddef>

#define HD   128
#define NMAX 100000
#define GMAX 1024
#define ELLW 64

// ---------------- scratch (device globals; no allocation allowed) ----------
__device__ __align__(256) __half g_msg[NMAX * HD];            // m' fp16 = (h @ W) * dinv[row]
__device__ __align__(256) __nv_bfloat16 g_h[NMAX * HD];       // h bf16 (GEMM A input)
__device__ __align__(256) __nv_bfloat16 g_whi[4 * HD * HD];   // W^T split hi ([N,K] row-major)
__device__ __align__(256) __nv_bfloat16 g_wlo[4 * HD * HD];   // W^T split lo
__device__ __align__(256) int   g_ell[NMAX * ELLW];
__device__ __align__(256) int   g_cnt[NMAX];
__device__ __align__(256) float g_pooled[GMAX * HD];
__device__ __align__(256) float g_counts[GMAX];

// ---------------- helpers ----------------------------------------------------
__device__ __forceinline__ uint32_t smem_u32(const void* p) {
    uint32_t a;
    asm("{ .reg .u64 t; cvta.to.shared.u64 t, %1; cvt.u32.u64 %0, t; }" : "=r"(a) : "l"(p));
    return a;
}

__device__ __forceinline__ void ldm4(uint32_t* r, uint32_t addr) {
    asm volatile("ldmatrix.sync.aligned.m8n8.x4.shared.b16 {%0,%1,%2,%3}, [%4];"
                 : "=r"(r[0]), "=r"(r[1]), "=r"(r[2]), "=r"(r[3]) : "r"(addr));
}

__device__ __forceinline__ void mma_bf16(float* c, const uint32_t* a,
                                         uint32_t b0, uint32_t b1) {
    asm volatile(
        "mma.sync.aligned.m16n8k16.row.col.f32.bf16.bf16.f32 "
        "{%0,%1,%2,%3}, {%4,%5,%6,%7}, {%8,%9}, {%0,%1,%2,%3};"
        : "+f"(c[0]), "+f"(c[1]), "+f"(c[2]), "+f"(c[3])
        : "r"(a[0]), "r"(a[1]), "r"(a[2]), "r"(a[3]), "r"(b0), "r"(b1));
}

__device__ __forceinline__ uint32_t pack_bf16x2(float x, float y) {
    __nv_bfloat162 b = {__float2bfloat16(x), __float2bfloat16(y)};
    return *(uint32_t*)&b;
}

// SMEM plan: padded rows, stride 136 bf16 = 272 bytes (conflict-free ldmatrix)
#define ROWB 272
#define SA    0
#define SW_HI (SA + 64 * ROWB)
#define SW_LO (SW_HI + 128 * ROWB)
#define S_TOT (SW_LO + 128 * ROWB)

#define GEMM_CTAS 296   // 2 per SM, persistent

// ---------------- persistent HMMA GEMM (2-pass bf16) -------------------------
// W hi/lo loaded into SMEM ONCE, then grid-stride over m-tiles.
// If xf != nullptr (layer 0), A is read from f32 x and converted in the fill.
// dinv computed inline from cnt: rsqrt(cnt+1).
__global__ __launch_bounds__(256, 2) void gemm_hmma(
    const __nv_bfloat16* __restrict__ A, const float* __restrict__ xf,
    const __nv_bfloat16* __restrict__ Whi, const __nv_bfloat16* __restrict__ Wlo,
    const int* __restrict__ cnt, __half* __restrict__ M, int n, int ntiles)
{
    extern __shared__ char smem[];
    const uint32_t sb = smem_u32(smem);
    const int tid = threadIdx.x;

    // ---- load W tiles once ----
#pragma unroll
    for (int i = 0; i < 8; i++) {                    // 128 rows x 16 uint4 each
        int idx = tid + i * 256;
        int r = idx >> 4, c = idx & 15;
        *(uint4*)(smem + SW_HI + r * ROWB + c * 16) =
            *(const uint4*)(Whi + (size_t)r * HD + c * 8);
        *(uint4*)(smem + SW_LO + r * ROWB + c * 16) =
            *(const uint4*)(Wlo + (size_t)r * HD + c * 8);
    }

    const int wid = tid >> 5, lane = tid & 31;
    const int mstrip = wid & 3;
    const int nhalf  = wid >> 2;
    const int lrow = lane & 15, lcol = lane >> 4;

    const uint32_t a0    = sb + SA    + (mstrip * 16 + lrow) * ROWB + lcol * 16;
    const uint32_t w_hi0 = sb + SW_HI + (nhalf * 64 + lrow) * ROWB + lcol * 16;
    const uint32_t w_lo0 = sb + SW_LO + (nhalf * 64 + lrow) * ROWB + lcol * 16;
    const uint4 z4 = make_uint4(0, 0, 0, 0);

    for (int tile = blockIdx.x; tile < ntiles; tile += GEMM_CTAS) {
        const int row0 = tile * 64;

        // ---- fill A tile: 64 rows x 16 uint4 ----
#pragma unroll
        for (int i = 0; i < 4; i++) {
            int idx = tid + i * 256;
            int r = idx >> 4, c = idx & 15;
            int gr = row0 + r;
            uint4 v = z4;
            if (gr < n) {
                if (xf) {
                    const float* srcp = xf + (size_t)gr * HD + c * 8;
                    float4 f0 = *(const float4*)(srcp);
                    float4 f1 = *(const float4*)(srcp + 4);
                    v.x = pack_bf16x2(f0.x, f0.y);
                    v.y = pack_bf16x2(f0.z, f0.w);
                    v.z = pack_bf16x2(f1.x, f1.y);
                    v.w = pack_bf16x2(f1.z, f1.w);
                } else {
                    v = *(const uint4*)(A + (size_t)gr * HD + c * 8);
                }
            }
            *(uint4*)(smem + SA + r * ROWB + c * 16) = v;
        }
        __syncthreads();

        // ---- compute ----
        float acc[8][4];
#pragma unroll
        for (int p = 0; p < 8; p++)
#pragma unroll
            for (int j = 0; j < 4; j++) acc[p][j] = 0.0f;

#pragma unroll
        for (int ks = 0; ks < 8; ks++) {
            uint32_t a[4];
            ldm4(a, a0 + ks * 32);
#pragma unroll
            for (int p = 0; p < 4; p++) {
                uint32_t wh[4], wl[4];
                ldm4(wh, w_hi0 + p * (16 * ROWB) + ks * 32);
                mma_bf16(acc[2 * p],     a, wh[0], wh[2]);
                mma_bf16(acc[2 * p + 1], a, wh[1], wh[3]);
                ldm4(wl, w_lo0 + p * (16 * ROWB) + ks * 32);
                mma_bf16(acc[2 * p],     a, wl[0], wl[2]);
                mma_bf16(acc[2 * p + 1], a, wl[1], wl[3]);
            }
        }

        // ---- epilogue: scale by rsqrt(cnt+1), store fp16 ----
        const int rbase = row0 + mstrip * 16 + (lane >> 2);
        const int qc = (lane & 3) * 2;
#pragma unroll
        for (int rr = 0; rr < 2; rr++) {
            int row = rbase + rr * 8;
            if (row < n) {
                float w = rsqrtf((float)cnt[row] + 1.0f);
                __half* dst = M + (size_t)row * HD + nhalf * 64 + qc;
#pragma unroll
                for (int p = 0; p < 8; p++) {
                    __half2 v = __floats2half2_rn(acc[p][rr * 2] * w, acc[p][rr * 2 + 1] * w);
                    *(__half2*)(dst + p * 8) = v;
                }
            }
        }
        __syncthreads();   // A tile reuse barrier
    }
}

// ---------------- setup1: zero cnt/pooled/counts + weight split --------------
__global__ void setup1(int* __restrict__ cnt, float* __restrict__ pooled,
                       float* __restrict__ counts,
                       const float* __restrict__ W0, const float* __restrict__ W1,
                       const float* __restrict__ W2, const float* __restrict__ W3,
                       __nv_bfloat16* __restrict__ Bhi, __nv_bfloat16* __restrict__ Blo,
                       int n, int G)
{
    int i = blockIdx.x * blockDim.x + threadIdx.x;
    if (i < n) cnt[i] = 0;
    if (i < G * HD) pooled[i] = 0.0f;
    if (i < G) counts[i] = 0.0f;
    if (i < 4 * HD * HD) {
        int l = i >> 14;
        int r = i & (HD * HD - 1);
        const float* W = (l == 0) ? W0 : (l == 1) ? W1 : (l == 2) ? W2 : W3;
        int nn = r >> 7, kk = r & 127;
        float v = W[kk * HD + nn];
        __nv_bfloat16 hi = __float2bfloat16(v);
        __nv_bfloat16 lo = __float2bfloat16(v - __bfloat162float(hi));
        Bhi[i] = hi;
        Blo[i] = lo;
    }
}

// ---------------- setup2: ELL fill + batch histogram --------------------------
__global__ void setup2(const int* __restrict__ src, const int* __restrict__ dst,
                       int* __restrict__ cnt, int* __restrict__ ell,
                       const int* __restrict__ batch, float* __restrict__ counts,
                       int E, int n)
{
    int i = blockIdx.x * blockDim.x + threadIdx.x;
    if (i < E) {
        int d = dst[i];
        int pos = atomicAdd(&cnt[d], 1);
        if (pos < ELLW) ell[(size_t)d * ELLW + pos] = src[i];
    }
    if (i < n) atomicAdd(&counts[batch[i]], 1.0f);
}

// ---------------- fused gather + selfloop + bias + relu (+ pool on last) ----
// one warp per dst node, fp16 messages: lane covers 4 channels (8 bytes)
__global__ __launch_bounds__(256) void gather_nodes(
    const __half* __restrict__ m, const int* __restrict__ ell,
    const int* __restrict__ cnt, const float* __restrict__ bias,
    __nv_bfloat16* __restrict__ out_h,
    const int* __restrict__ batch, float* __restrict__ pooled,
    int mode, int n)
{
    int d = blockIdx.x * (blockDim.x >> 5) + (threadIdx.x >> 5);
    if (d >= n) return;
    const int lane = threadIdx.x & 31;
    const int c4 = lane << 2;

    // self term
    uint2 sraw = *(const uint2*)(m + (size_t)d * HD + c4);
    float2 s0 = __half22float2(*(const __half2*)&sraw.x);
    float2 s1 = __half22float2(*(const __half2*)&sraw.y);
    float a0 = s0.x, a1 = s0.y, a2 = s1.x, a3 = s1.y;

    const int deg = cnt[d];
    const int* row = ell + (size_t)d * ELLW;

    for (int base = 0; base < deg; base += 32) {
        int idx = (base + lane < deg) ? __ldg(row + base + lane) : 0;
        int lim = min(32, deg - base);
#pragma unroll 8
        for (int j = 0; j < lim; j++) {
            int s = __shfl_sync(0xffffffffu, idx, j);
            uint2 raw = *(const uint2*)(m + (size_t)s * HD + c4);
            float2 v0 = __half22float2(*(const __half2*)&raw.x);
            float2 v1 = __half22float2(*(const __half2*)&raw.y);
            a0 += v0.x; a1 += v0.y; a2 += v1.x; a3 += v1.y;
        }
    }

    float w = rsqrtf((float)deg + 1.0f);
    float4 bb = *(const float4*)(bias + c4);
    float o0 = fmaxf(fmaf(a0, w, bb.x), 0.f);
    float o1 = fmaxf(fmaf(a1, w, bb.y), 0.f);
    float o2 = fmaxf(fmaf(a2, w, bb.z), 0.f);
    float o3 = fmaxf(fmaf(a3, w, bb.w), 0.f);

    if (mode == 0) {
        __nv_bfloat162 h0 = {__float2bfloat16(o0), __float2bfloat16(o1)};
        __nv_bfloat162 h1 = {__float2bfloat16(o2), __float2bfloat16(o3)};
        *(__nv_bfloat162*)(out_h + (size_t)d * HD + c4)     = h0;
        *(__nv_bfloat162*)(out_h + (size_t)d * HD + c4 + 2) = h1;
    } else {
        int g = batch[d];
        float* p = pooled + (size_t)g * HD + c4;
        asm volatile("red.global.add.v4.f32 [%0], {%1, %2, %3, %4};"
                     :: "l"(p), "f"(o0), "f"(o1), "f"(o2), "f"(o3) : "memory");
    }
}

// ---------------- final linear head --------------------------------------------
__global__ void final_linear(const float* __restrict__ pooled, const float* __restrict__ counts,
                             const float* __restrict__ linW, const float* __restrict__ linb,
                             float* __restrict__ out)
{
    int g = blockIdx.x;
    int c = threadIdx.x;
    float cntv = fmaxf(counts[g], 1.0f);
    float p = pooled[g * HD + c] / cntv;
    float v0 = p * linW[c * 2 + 0];
    float v1 = p * linW[c * 2 + 1];
#pragma unroll
    for (int o = 16; o > 0; o >>= 1) {
        v0 += __shfl_xor_sync(0xffffffffu, v0, o);
        v1 += __shfl_xor_sync(0xffffffffu, v1, o);
    }
    __shared__ float s0[4], s1[4];
    int w = threadIdx.x >> 5;
    if ((threadIdx.x & 31) == 0) { s0[w] = v0; s1[w] = v1; }
    __syncthreads();
    if (threadIdx.x == 0) {
        out[g * 2 + 0] = s0[0] + s0[1] + s0[2] + s0[3] + linb[0];
        out[g * 2 + 1] = s1[0] + s1[1] + s1[2] + s1[3] + linb[1];
    }
}

// ---------------- launch ---------------------------------------------------------
extern "C" void kernel_launch(void* const* d_in, const int* in_sizes, int n_in,
                              void* d_out, int out_size)
{
    const float* x     = (const float*)d_in[0];
    const int*   ei    = (const int*)d_in[1];
    const int*   batch = (const int*)d_in[2];
    const float* W[4]  = {(const float*)d_in[3], (const float*)d_in[5],
                          (const float*)d_in[7], (const float*)d_in[9]};
    const float* bv[4] = {(const float*)d_in[4], (const float*)d_in[6],
                          (const float*)d_in[8], (const float*)d_in[10]};
    const float* linW  = (const float*)d_in[11];
    const float* linb  = (const float*)d_in[12];
    float* out = (float*)d_out;

    const int n = in_sizes[0] / HD;
    const int E = in_sizes[1] / 2;
    const int G = out_size / 2;
    const int* src = ei;
    const int* dst = ei + E;

    float *pooled, *counts;
    __half* msg;
    int *ell, *cnt;
    __nv_bfloat16 *hbuf, *whi, *wlo;
    cudaGetSymbolAddress((void**)&msg,    g_msg);
    cudaGetSymbolAddress((void**)&hbuf,   g_h);
    cudaGetSymbolAddress((void**)&whi,    g_whi);
    cudaGetSymbolAddress((void**)&wlo,    g_wlo);
    cudaGetSymbolAddress((void**)&ell,    g_ell);
    cudaGetSymbolAddress((void**)&cnt,    g_cnt);
    cudaGetSymbolAddress((void**)&pooled, g_pooled);
    cudaGetSymbolAddress((void**)&counts, g_counts);

    cudaFuncSetAttribute(gemm_hmma, cudaFuncAttributeMaxDynamicSharedMemorySize, S_TOT);

    // setup (2 launches)
    int s1n = n;
    if (G * HD > s1n) s1n = G * HD;
    if (4 * HD * HD > s1n) s1n = 4 * HD * HD;
    setup1<<<(s1n + 255) / 256, 256>>>(cnt, pooled, counts,
                                       W[0], W[1], W[2], W[3], whi, wlo, n, G);
    int s2n = (E > n) ? E : n;
    setup2<<<(s2n + 255) / 256, 256>>>(src, dst, cnt, ell, batch, counts, E, n);

    const int ntiles = (n + 63) / 64;
    for (int l = 0; l < 4; l++) {
        gemm_hmma<<<GEMM_CTAS, 256, S_TOT>>>(hbuf, (l == 0) ? x : nullptr,
                                             whi + l * HD * HD, wlo + l * HD * HD,
                                             cnt, msg, n, ntiles);
        gather_nodes<<<(n + 7) / 8, 256>>>(msg, ell, cnt, bv[l],
                                           hbuf, batch, pooled, (l == 3) ? 1 : 0, n);
    }

    final_linear<<<G, 128>>>(pooled, counts, linW, linb, out);
}